// round 1
// baseline (speedup 1.0000x reference)
#include <cuda_runtime.h>
#include <math.h>

#define MROWS 32768     // B*L
#define DD 512
#define PP 512
#define LSEQ 4096
#define NB 8
#define NLAYER 3
#define NC 32           // scan chunks
#define CL 128          // chunk length (NC*CL == LSEQ)

// ---------------- scratch (device globals; no allocation) ----------------
__device__ __align__(256) float g_h  [(size_t)MROWS * DD];
__device__ __align__(256) float g_b1 [(size_t)MROWS * DD];
__device__ __align__(256) float g_b2 [(size_t)MROWS * DD];
__device__ __align__(256) float g_big[(size_t)MROWS * 2 * DD];  // Bu/xs/e
__device__ __align__(256) float g_wbar[2 * PP * DD];
__device__ __align__(256) float g_wc [DD * 2 * PP];
__device__ __align__(256) float g_wenc[DD * 64];
__device__ __align__(256) float2 g_lb[PP];
__device__ __align__(256) float2 g_lbN[PP];
__device__ __align__(256) float2 g_coef[PP];
__device__ __align__(256) float2 g_carry[NB * NC * PP];

__device__ __forceinline__ float geluf(float x) {
    return 0.5f * x * (1.0f + erff(x * 0.70710678118654752f));
}

// ---------------- generic NT GEMM: C[m,n] = sum_k A[m,k] * W[n,k] ----------------
// A row-major (M, lda>=K), W row-major (N, K). M%128==0, N%64==0, K%16==0.
// EPI: 0 = store; 1 = +vec[n] store; 2 = s5 epilogue; 3 = residual into C (+mat)
#define BM 128
#define BN 64
#define BK 16

template <int EPI>
__global__ void __launch_bounds__(256, 2)
gemm_nt(const float* __restrict__ A, int lda,
        const float* __restrict__ W,
        float* __restrict__ C, int ldc,
        int M, int N, int K,
        const float* __restrict__ vec,
        const float* __restrict__ mat, int ldm)
{
    __shared__ float As[BK][BM + 4];
    __shared__ float Ws[BK][BN + 4];

    const int tid = threadIdx.x;
    const int bm = blockIdx.y * BM;
    const int bn = blockIdx.x * BN;
    const int tx = tid & 15;   // n: 4 cols
    const int ty = tid >> 4;   // m: 8 rows

    float acc[8][4];
#pragma unroll
    for (int i = 0; i < 8; i++)
#pragma unroll
        for (int j = 0; j < 4; j++) acc[i][j] = 0.f;

    for (int k0 = 0; k0 < K; k0 += BK) {
        // load A tile: 128 rows x 16 k = 512 float4
#pragma unroll
        for (int q = 0; q < 2; q++) {
            int idx = tid + q * 256;
            int row = idx >> 2;
            int kq = (idx & 3) * 4;
            float4 v = *(const float4*)&A[(size_t)(bm + row) * lda + k0 + kq];
            As[kq + 0][row] = v.x; As[kq + 1][row] = v.y;
            As[kq + 2][row] = v.z; As[kq + 3][row] = v.w;
        }
        {
            int row = tid >> 2;
            int kq = (tid & 3) * 4;
            float4 v = *(const float4*)&W[(size_t)(bn + row) * K + k0 + kq];
            Ws[kq + 0][row] = v.x; Ws[kq + 1][row] = v.y;
            Ws[kq + 2][row] = v.z; Ws[kq + 3][row] = v.w;
        }
        __syncthreads();
#pragma unroll
        for (int k = 0; k < BK; k++) {
            float a0[8], b0[4];
            *(float4*)&a0[0] = *(const float4*)&As[k][ty * 8];
            *(float4*)&a0[4] = *(const float4*)&As[k][ty * 8 + 4];
            *(float4*)&b0[0] = *(const float4*)&Ws[k][tx * 4];
#pragma unroll
            for (int i = 0; i < 8; i++)
#pragma unroll
                for (int j = 0; j < 4; j++) acc[i][j] = fmaf(a0[i], b0[j], acc[i][j]);
        }
        __syncthreads();
    }

#pragma unroll
    for (int i = 0; i < 8; i++) {
        int m = bm + ty * 8 + i;
#pragma unroll
        for (int j = 0; j < 4; j++) {
            int n = bn + tx * 4 + j;
            float v = acc[i][j];
            if (EPI == 0) {
                C[(size_t)m * ldc + n] = v;
            } else if (EPI == 1) {
                C[(size_t)m * ldc + n] = v + vec[n];
            } else if (EPI == 2) {
                float u = mat[(size_t)m * ldm + n];
                C[(size_t)m * ldc + n] = geluf(v + vec[n] * u) + u;
            } else { // EPI == 3: h += acc + fx2
                float u = mat[(size_t)m * ldm + n];
                C[(size_t)m * ldc + n] += v + u;
            }
        }
    }
}

// ---------------- LayerNorm kernels (row of 512) ----------------
__global__ void ln_double_kernel(const float* __restrict__ in, float* __restrict__ out,
                                 const float* __restrict__ w1, const float* __restrict__ b1,
                                 const float* __restrict__ w2, const float* __restrict__ b2)
{
    const int row = blockIdx.x;
    const int t = threadIdx.x;  // 256
    const float* x = in + (size_t)row * DD;
    float v0 = x[t], v1 = x[t + 256];
    __shared__ float red[256];

    red[t] = v0 + v1; __syncthreads();
    for (int s = 128; s > 0; s >>= 1) { if (t < s) red[t] += red[t + s]; __syncthreads(); }
    float mean = red[0] * (1.f / 512.f);
    __syncthreads();
    float d0 = v0 - mean, d1 = v1 - mean;
    red[t] = d0 * d0 + d1 * d1; __syncthreads();
    for (int s = 128; s > 0; s >>= 1) { if (t < s) red[t] += red[t + s]; __syncthreads(); }
    float rs = rsqrtf(red[0] * (1.f / 512.f) + 1e-5f);
    __syncthreads();
    float y0 = d0 * rs * w1[t] + b1[t];
    float y1 = d1 * rs * w1[t + 256] + b1[t + 256];

    red[t] = y0 + y1; __syncthreads();
    for (int s = 128; s > 0; s >>= 1) { if (t < s) red[t] += red[t + s]; __syncthreads(); }
    float mean2 = red[0] * (1.f / 512.f);
    __syncthreads();
    float e0 = y0 - mean2, e1 = y1 - mean2;
    red[t] = e0 * e0 + e1 * e1; __syncthreads();
    for (int s = 128; s > 0; s >>= 1) { if (t < s) red[t] += red[t + s]; __syncthreads(); }
    float rs2 = rsqrtf(red[0] * (1.f / 512.f) + 1e-5f);
    out[(size_t)row * DD + t]       = e0 * rs2 * w2[t] + b2[t];
    out[(size_t)row * DD + t + 256] = e1 * rs2 * w2[t + 256] + b2[t + 256];
}

__global__ void ln_kernel(const float* __restrict__ in, float* __restrict__ out,
                          const float* __restrict__ w, const float* __restrict__ b)
{
    const int row = blockIdx.x;
    const int t = threadIdx.x;
    const float* x = in + (size_t)row * DD;
    float v0 = x[t], v1 = x[t + 256];
    __shared__ float red[256];
    red[t] = v0 + v1; __syncthreads();
    for (int s = 128; s > 0; s >>= 1) { if (t < s) red[t] += red[t + s]; __syncthreads(); }
    float mean = red[0] * (1.f / 512.f);
    __syncthreads();
    float d0 = v0 - mean, d1 = v1 - mean;
    red[t] = d0 * d0 + d1 * d1; __syncthreads();
    for (int s = 128; s > 0; s >>= 1) { if (t < s) red[t] += red[t + s]; __syncthreads(); }
    float rs = rsqrtf(red[0] * (1.f / 512.f) + 1e-5f);
    out[(size_t)row * DD + t]       = d0 * rs * w[t] + b[t];
    out[(size_t)row * DD + t + 256] = d1 * rs * w[t + 256] + b[t + 256];
}

// ---------------- S5 per-layer param prep ----------------
__global__ void prep_scalars(const float* __restrict__ lam_re, const float* __restrict__ lam_im,
                             const float* __restrict__ log_step)
{
    int p = blockIdx.x * blockDim.x + threadIdx.x;
    if (p >= PP) return;
    float lr = lam_re[p], li = lam_im[p];
    float st = expf(log_step[p]);
    float er = expf(lr * st);
    float c = er * cosf(li * st);
    float s = er * sinf(li * st);
    g_lb[p] = make_float2(c, s);
    // lb^CL (CL=128 -> 7 squarings)
    float ar = c, ai = s;
#pragma unroll
    for (int i = 0; i < 7; i++) {
        float nr = ar * ar - ai * ai;
        float ni = 2.f * ar * ai;
        ar = nr; ai = ni;
    }
    g_lbN[p] = make_float2(ar, ai);
    // (lb - 1) / lam
    float den = lr * lr + li * li;
    float cr = ((c - 1.f) * lr + s * li) / den;
    float ci = (s * lr - (c - 1.f) * li) / den;
    g_coef[p] = make_float2(cr, ci);
}

__global__ void prep_wbar(const float* __restrict__ Bre, const float* __restrict__ Bim)
{
    int idx = blockIdx.x * blockDim.x + threadIdx.x;   // P*D
    if (idx >= PP * DD) return;
    int p = idx / DD;
    float2 cf = g_coef[p];
    float br = Bre[idx], bi = Bim[idx];
    int d = idx - p * DD;
    g_wbar[(size_t)p * DD + d]        = cf.x * br - cf.y * bi;
    g_wbar[(size_t)(PP + p) * DD + d] = cf.x * bi + cf.y * br;
}

__global__ void prep_wc(const float* __restrict__ Cre, const float* __restrict__ Cim)
{
    int idx = blockIdx.x * blockDim.x + threadIdx.x;   // D*P
    if (idx >= DD * PP) return;
    int d = idx / PP;
    int p = idx - d * PP;
    g_wc[(size_t)d * (2 * PP) + p]      = 2.f * Cre[idx];
    g_wc[(size_t)d * (2 * PP) + PP + p] = -2.f * Cim[idx];
}

__global__ void transpose_enc(const float* __restrict__ w)  // (64, 512) -> (512, 64)
{
    int idx = blockIdx.x * blockDim.x + threadIdx.x;
    if (idx >= 64 * DD) return;
    int k = idx / DD, n = idx - k * DD;
    g_wenc[(size_t)n * 64 + k] = w[idx];
}

// ---------------- chunked complex scan over g_big (in-place) ----------------
__global__ void scan_pass1()
{
    const int p = threadIdx.x;
    const int c = blockIdx.x, b = blockIdx.y;
    float2 lb = g_lb[p];
    float xr = 0.f, xi = 0.f;
    const float* bu = g_big + ((size_t)(b * LSEQ + c * CL)) * 1024 + p;
    for (int t = 0; t < CL; t++) {
        float br = bu[0], bi = bu[512];
        float nr = fmaf(lb.x, xr, fmaf(-lb.y, xi, br));
        float ni = fmaf(lb.x, xi, fmaf(lb.y, xr, bi));
        xr = nr; xi = ni;
        bu += 1024;
    }
    g_carry[((size_t)b * NC + c) * PP + p] = make_float2(xr, xi);
}

__global__ void scan_pass2()
{
    const int p = threadIdx.x;
    const int b = blockIdx.x;
    float2 A = g_lbN[p];
    float xr = 0.f, xi = 0.f;
#pragma unroll
    for (int c = 0; c < NC; c++) {
        size_t idx = ((size_t)b * NC + c) * PP + p;
        float2 v = g_carry[idx];
        g_carry[idx] = make_float2(xr, xi);   // exclusive prefix
        float nr = fmaf(A.x, xr, fmaf(-A.y, xi, v.x));
        float ni = fmaf(A.x, xi, fmaf(A.y, xr, v.y));
        xr = nr; xi = ni;
    }
}

__global__ void scan_pass3()
{
    const int p = threadIdx.x;
    const int c = blockIdx.x, b = blockIdx.y;
    float2 lb = g_lb[p];
    float2 cv = g_carry[((size_t)b * NC + c) * PP + p];
    float xr = cv.x, xi = cv.y;
    float* bu = g_big + ((size_t)(b * LSEQ + c * CL)) * 1024 + p;
    for (int t = 0; t < CL; t++) {
        float br = bu[0], bi = bu[512];
        float nr = fmaf(lb.x, xr, fmaf(-lb.y, xi, br));
        float ni = fmaf(lb.x, xi, fmaf(lb.y, xr, bi));
        xr = nr; xi = ni;
        bu[0] = xr; bu[512] = xi;
        bu += 1024;
    }
}

// ---------------- GEGLU elementwise (in-place on g_big) ----------------
__global__ void glu_kernel()
{
    size_t idx = (size_t)blockIdx.x * blockDim.x + threadIdx.x;   // MROWS*128 float4s
    if (idx >= (size_t)MROWS * 128) return;
    size_t m = idx >> 7;
    size_t q = idx & 127;
    float4* row = (float4*)(g_big + m * 1024);
    float4 a = row[q];
    float4 g = row[q + 128];
    a.x *= geluf(g.x); a.y *= geluf(g.y); a.z *= geluf(g.z); a.w *= geluf(g.w);
    row[q] = a;
}

// ---------------- masked mean pool + head ----------------
__global__ void pool_head(const int* __restrict__ lengths,
                          const float* __restrict__ hw, const float* __restrict__ hb,
                          float* __restrict__ out)
{
    const int b = blockIdx.x;
    const int d = threadIdx.x;  // 512
    int len = lengths[b];
    const float* hp = g_h + ((size_t)b * LSEQ) * DD + d;
    float s = 0.f;
    for (int t = 0; t < len; t++) s += hp[(size_t)t * DD];
    int den = len > 1 ? len : 1;
    float v = (s / (float)den) * hw[d];
    __shared__ float red[512];
    red[d] = v; __syncthreads();
    for (int st = 256; st > 0; st >>= 1) { if (d < st) red[d] += red[d + st]; __syncthreads(); }
    if (d == 0) out[b] = red[0] + hb[0];
}

// ---------------- launch ----------------
extern "C" void kernel_launch(void* const* d_in, const int* in_sizes, int n_in,
                              void* d_out, int out_size)
{
    const float* x       = (const float*)d_in[0];
    const int*   lengths = (const int*)  d_in[1];
    const float* enc_w   = (const float*)d_in[2];
    const float* enc_b   = (const float*)d_in[3];
    const float* lam_re  = (const float*)d_in[4];
    const float* lam_im  = (const float*)d_in[5];
    const float* Bre     = (const float*)d_in[6];
    const float* Bim     = (const float*)d_in[7];
    const float* Cre     = (const float*)d_in[8];
    const float* Cim     = (const float*)d_in[9];
    const float* Dp      = (const float*)d_in[10];
    const float* log_step= (const float*)d_in[11];
    const float* an_w    = (const float*)d_in[12];
    const float* an_b    = (const float*)d_in[13];
    const float* fn_w    = (const float*)d_in[14];
    const float* fn_b    = (const float*)d_in[15];
    const float* ffe_w   = (const float*)d_in[16];
    const float* ffd_w   = (const float*)d_in[17];
    const float* norm_w  = (const float*)d_in[18];
    const float* norm_b  = (const float*)d_in[19];
    const float* head_w  = (const float*)d_in[20];
    const float* head_b  = (const float*)d_in[21];
    float* out = (float*)d_out;

    void *p_h, *p_b1, *p_b2, *p_big, *p_wbar, *p_wc, *p_wenc;
    cudaGetSymbolAddress(&p_h, g_h);
    cudaGetSymbolAddress(&p_b1, g_b1);
    cudaGetSymbolAddress(&p_b2, g_b2);
    cudaGetSymbolAddress(&p_big, g_big);
    cudaGetSymbolAddress(&p_wbar, g_wbar);
    cudaGetSymbolAddress(&p_wc, g_wc);
    cudaGetSymbolAddress(&p_wenc, g_wenc);
    float* h   = (float*)p_h;
    float* b1  = (float*)p_b1;
    float* b2  = (float*)p_b2;
    float* big = (float*)p_big;
    float* wbar= (float*)p_wbar;
    float* wc  = (float*)p_wc;
    float* wenc= (float*)p_wenc;

    const dim3 blk(256);

    // encoder: h = x @ enc_w + enc_b
    transpose_enc<<<(64 * DD + 255) / 256, blk>>>(enc_w);
    gemm_nt<1><<<dim3(DD / BN, MROWS / BM), blk>>>(x, 64, wenc, h, DD,
                                                   MROWS, DD, 64, enc_b, nullptr, 0);

    for (int i = 0; i < NLAYER; i++) {
        // fx = LN(LN(h, norm), an)
        ln_double_kernel<<<MROWS, blk>>>(h, b1,
                                         norm_w + i * DD, norm_b + i * DD,
                                         an_w + i * DD, an_b + i * DD);
        // discretized params
        prep_scalars<<<2, 256>>>(lam_re + i * PP, lam_im + i * PP, log_step + i * PP);
        prep_wbar<<<(PP * DD + 255) / 256, blk>>>(Bre + (size_t)i * PP * DD, Bim + (size_t)i * PP * DD);
        prep_wc  <<<(DD * PP + 255) / 256, blk>>>(Cre + (size_t)i * DD * PP, Cim + (size_t)i * DD * PP);
        // Bu = fx @ Wbar^T  (re || im)
        gemm_nt<0><<<dim3(1024 / BN, MROWS / BM), blk>>>(b1, DD, wbar, big, 1024,
                                                         MROWS, 1024, DD, nullptr, nullptr, 0);
        // scan
        scan_pass1<<<dim3(NC, NB), 512>>>();
        scan_pass2<<<NB, 512>>>();
        scan_pass3<<<dim3(NC, NB), 512>>>();
        // z = gelu(2Re(xs@C^T) + Dp*fx) + fx
        gemm_nt<2><<<dim3(DD / BN, MROWS / BM), blk>>>(big, 1024, wc, b2, DD,
                                                       MROWS, DD, 1024, Dp + i * DD, b1, DD);
        // fx2 = LN(z, fn)
        ln_kernel<<<MROWS, blk>>>(b2, b1, fn_w + i * DD, fn_b + i * DD);
        // e = fx2 @ ffe^T
        gemm_nt<0><<<dim3(1024 / BN, MROWS / BM), blk>>>(b1, DD, ffe_w + (size_t)i * 1024 * DD,
                                                         big, 1024, MROWS, 1024, DD,
                                                         nullptr, nullptr, 0);
        // m = a * gelu(g) (in place, first half of e rows)
        glu_kernel<<<((unsigned)((size_t)MROWS * 128 + 255) / 256), blk>>>();
        // h += m @ ffd^T + fx2
        gemm_nt<3><<<dim3(DD / BN, MROWS / BM), blk>>>(big, 1024, ffd_w + (size_t)i * DD * DD,
                                                       h, DD, MROWS, DD, DD,
                                                       nullptr, b1, DD);
    }

    pool_head<<<NB, 512>>>(lengths, head_w, head_b, out);
}

// round 5
// speedup vs baseline: 1.8205x; 1.8205x over previous
#include <cuda_runtime.h>
#include <cuda_bf16.h>
#include <math.h>
#include <stdint.h>

#define MR 32768
#define LSEQ 4096
#define NBATCH 8
#define NLAYER 3
#define NCHK 32
#define CLEN 128

typedef __nv_bfloat16 bf16;

// ---------------- scratch ----------------
__device__ __align__(256) float g_h  [(size_t)MR * 512];
__device__ __align__(256) float g_b1 [(size_t)MR * 512];
__device__ __align__(256) float g_b2 [(size_t)MR * 512];
__device__ __align__(256) float g_big[(size_t)MR * 1024];
__device__ __align__(256) bf16 g_b1h[(size_t)MR * 512];
__device__ __align__(256) bf16 g_b1l[(size_t)MR * 512];
__device__ __align__(256) bf16 g_xh [(size_t)MR * 1024];
__device__ __align__(256) bf16 g_xl [(size_t)MR * 1024];
__device__ __align__(256) bf16 g_xbh[(size_t)MR * 64];
__device__ __align__(256) bf16 g_xbl[(size_t)MR * 64];
__device__ __align__(256) bf16 g_wbh[1024 * 512];
__device__ __align__(256) bf16 g_wbl[1024 * 512];
__device__ __align__(256) bf16 g_wch[512 * 1024];
__device__ __align__(256) bf16 g_wcl[512 * 1024];
__device__ __align__(256) bf16 g_feh[1024 * 512];
__device__ __align__(256) bf16 g_fel[1024 * 512];
__device__ __align__(256) bf16 g_fdh[512 * 512];
__device__ __align__(256) bf16 g_fdl[512 * 512];
__device__ __align__(256) bf16 g_weh[512 * 64];
__device__ __align__(256) bf16 g_wel[512 * 64];
__device__ __align__(256) float2 g_lb[512];
__device__ __align__(256) float2 g_lbN[512];
__device__ __align__(256) float2 g_coef[512];
__device__ __align__(256) float2 g_carry[NBATCH * NCHK * 512];

__device__ __forceinline__ float geluf(float x) {
    return 0.5f * x * (1.0f + erff(x * 0.70710678118654752f));
}
__device__ __forceinline__ uint32_t s2u(const void* p) {
    uint32_t a;
    asm("{ .reg .u64 t; cvta.to.shared.u64 t, %1; cvt.u32.u64 %0, t; }" : "=r"(a) : "l"(p));
    return a;
}
__device__ __forceinline__ void split1(float v, bf16* oh, bf16* ol) {
    bf16 h = __float2bfloat16(v);
    *oh = h;
    *ol = __float2bfloat16(v - __bfloat162float(h));
}
__device__ __forceinline__ void split4(float4 y, bf16* oh, bf16* ol) {
    union { bf16 b[4]; uint2 u; } H, L;
    float f[4] = {y.x, y.y, y.z, y.w};
#pragma unroll
    for (int e = 0; e < 4; e++) {
        bf16 h = __float2bfloat16(f[e]);
        H.b[e] = h;
        L.b[e] = __float2bfloat16(f[e] - __bfloat162float(h));
    }
    *(uint2*)oh = H.u;
    *(uint2*)ol = L.u;
}

#define LDSM4(r0, r1, r2, r3, a) \
    asm volatile("ldmatrix.sync.aligned.m8n8.x4.shared.b16 {%0,%1,%2,%3}, [%4];" \
                 : "=r"(r0), "=r"(r1), "=r"(r2), "=r"(r3) : "r"(a))

#define MMA16816(c, a, b) \
    asm volatile("mma.sync.aligned.m16n8k16.row.col.f32.bf16.bf16.f32 " \
                 "{%0,%1,%2,%3}, {%4,%5,%6,%7}, {%8,%9}, {%0,%1,%2,%3};" \
                 : "+f"((c)[0]), "+f"((c)[1]), "+f"((c)[2]), "+f"((c)[3]) \
                 : "r"((a)[0]), "r"((a)[1]), "r"((a)[2]), "r"((a)[3]), \
                   "r"((b)[0]), "r"((b)[1]))

// ---------------- HMMA GEMM: acc[m,n] = sum_k A[m,k]*W[n,k]; bf16 hi/lo 3-term -----
// Block 128x128, BK=32, 256 thr, 8 warps (4m x 2n), warp tile 32x64.
// smem stage: Ah[128][40] Al Bh Bl bf16 (80B padded rows). 2 stages = 81920 B.
// EPI: 0 store fp32; 1 +vec; 2 gelu(acc+vec[n]*u)+u; 3 C += acc+u; 4 GEGLU->bf16 hi/lo
#define STG 40960
#define GSMEM (2 * STG)

template <int EPI>
__global__ void __launch_bounds__(256, 1)
gemm_tc(const bf16* __restrict__ Ah, const bf16* __restrict__ Al, int lda,
        const bf16* __restrict__ Wh, const bf16* __restrict__ Wl, int K,
        float* __restrict__ C, int ldc,
        const float* __restrict__ vec, const float* __restrict__ mat,
        bf16* __restrict__ oh, bf16* __restrict__ ol)
{
    extern __shared__ char smembuf[];
    const uint32_t sb = s2u(smembuf);
    const int tid = threadIdx.x, lane = tid & 31, wid = tid >> 5;
    const int warpM = wid & 3, warpN = wid >> 2;
    const int bm = blockIdx.y << 7, bn = blockIdx.x << 7;
    const int NCH = K >> 5;

    float c[2][8][4];
#pragma unroll
    for (int i = 0; i < 2; i++)
#pragma unroll
        for (int j = 0; j < 8; j++)
#pragma unroll
            for (int q = 0; q < 4; q++) c[i][j][q] = 0.f;

    auto LOAD = [&](int ch) {
        int st = ch & 1;
        uint32_t base = sb + st * STG;
#pragma unroll
        for (int q = 0; q < 2; q++) {
            int chunk = tid + q * 256;
            int row = chunk >> 2, c16 = chunk & 3;
            const bf16* ga = Ah + (size_t)(bm + row) * lda + ch * 32 + c16 * 8;
            const bf16* gal = Al + (size_t)(bm + row) * lda + ch * 32 + c16 * 8;
            const bf16* gw = Wh + (size_t)(bn + row) * K + ch * 32 + c16 * 8;
            const bf16* gwl = Wl + (size_t)(bn + row) * K + ch * 32 + c16 * 8;
            uint32_t d = base + row * 80 + c16 * 16;
            asm volatile("cp.async.cg.shared.global [%0], [%1], 16;" :: "r"(d), "l"(ga) : "memory");
            asm volatile("cp.async.cg.shared.global [%0], [%1], 16;" :: "r"(d + 10240), "l"(gal) : "memory");
            asm volatile("cp.async.cg.shared.global [%0], [%1], 16;" :: "r"(d + 20480), "l"(gw) : "memory");
            asm volatile("cp.async.cg.shared.global [%0], [%1], 16;" :: "r"(d + 30720), "l"(gwl) : "memory");
        }
    };

    LOAD(0);
    asm volatile("cp.async.commit_group;" ::: "memory");

    for (int ch = 0; ch < NCH; ch++) {
        if (ch + 1 < NCH) LOAD(ch + 1);
        asm volatile("cp.async.commit_group;" ::: "memory");
        asm volatile("cp.async.wait_group 1;" ::: "memory");
        __syncthreads();

        uint32_t base = sb + (ch & 1) * STG;
#pragma unroll
        for (int kk = 0; kk < 2; kk++) {
            uint32_t kadd = kk * 32 + (lane >> 4) * 16;
            uint32_t ah[2][4], al[2][4], bh[8][2], bl[8][2];
#pragma unroll
            for (int mf = 0; mf < 2; mf++) {
                uint32_t row = warpM * 32 + mf * 16 + (lane & 15);
                uint32_t a0 = base + row * 80 + kadd;
                LDSM4(ah[mf][0], ah[mf][1], ah[mf][2], ah[mf][3], a0);
                LDSM4(al[mf][0], al[mf][1], al[mf][2], al[mf][3], a0 + 10240);
            }
#pragma unroll
            for (int g = 0; g < 4; g++) {
                uint32_t row = warpN * 64 + g * 16 + (lane & 15);
                uint32_t a0 = base + 20480 + row * 80 + kadd;
                uint32_t r0, r1, r2, r3;
                LDSM4(r0, r1, r2, r3, a0);
                bh[2*g][0] = r0; bh[2*g][1] = r2;
                bh[2*g+1][0] = r1; bh[2*g+1][1] = r3;
                LDSM4(r0, r1, r2, r3, a0 + 10240);
                bl[2*g][0] = r0; bl[2*g][1] = r2;
                bl[2*g+1][0] = r1; bl[2*g+1][1] = r3;
            }
#pragma unroll
            for (int mf = 0; mf < 2; mf++)
#pragma unroll
                for (int jb = 0; jb < 8; jb++) {
                    MMA16816(c[mf][jb], ah[mf], bh[jb]);
                    MMA16816(c[mf][jb], ah[mf], bl[jb]);
                    MMA16816(c[mf][jb], al[mf], bh[jb]);
                }
        }
        __syncthreads();
    }

    // ---------------- epilogue ----------------
#pragma unroll
    for (int mf = 0; mf < 2; mf++) {
        int m0 = bm + warpM * 32 + mf * 16 + (lane >> 2);
#pragma unroll
        for (int jb = 0; jb < 8; jb++) {
            int n = bn + warpN * 64 + jb * 8 + 2 * (lane & 3);
#pragma unroll
            for (int half = 0; half < 2; half++) {
                int r = m0 + half * 8;
                float v0 = c[mf][jb][2 * half], v1 = c[mf][jb][2 * half + 1];
                if (EPI == 4) {
                    int j = ((bn + warpN * 64 + jb * 8) >> 1) + (lane & 3);
                    size_t off = (size_t)r * 512 + j;
                    split1(v0 * geluf(v1), oh + off, ol + off);
                } else {
                    size_t off = (size_t)r * ldc + n;
                    if (EPI == 1) {
                        float2 bv = *(const float2*)(vec + n);
                        v0 += bv.x; v1 += bv.y;
                    } else if (EPI == 2) {
                        float2 u = *(const float2*)(mat + (size_t)r * ldc + n);
                        float2 dv = *(const float2*)(vec + n);
                        v0 = geluf(v0 + dv.x * u.x) + u.x;
                        v1 = geluf(v1 + dv.y * u.y) + u.y;
                    } else if (EPI == 3) {
                        float2 u = *(const float2*)(mat + (size_t)r * 512 + n);
                        float2 co = *(const float2*)(C + off);
                        v0 += co.x + u.x; v1 += co.y + u.y;
                    }
                    *(float2*)(C + off) = make_float2(v0, v1);
                }
            }
        }
    }
}

// ---------------- LayerNorm (warp per row) ----------------
__device__ __forceinline__ float wsum(float x) {
#pragma unroll
    for (int o = 16; o; o >>= 1) x += __shfl_xor_sync(0xFFFFFFFFu, x, o);
    return x;
}
__device__ __forceinline__ void ln_stage(float4 v[4], const float* __restrict__ w,
                                         const float* __restrict__ b, int l) {
    float s = 0.f;
#pragma unroll
    for (int q = 0; q < 4; q++) s += v[q].x + v[q].y + v[q].z + v[q].w;
    float mean = wsum(s) * (1.f / 512.f);
    float vv = 0.f;
#pragma unroll
    for (int q = 0; q < 4; q++) {
        v[q].x -= mean; v[q].y -= mean; v[q].z -= mean; v[q].w -= mean;
        vv += v[q].x * v[q].x + v[q].y * v[q].y + v[q].z * v[q].z + v[q].w * v[q].w;
    }
    float rs = rsqrtf(wsum(vv) * (1.f / 512.f) + 1e-5f);
#pragma unroll
    for (int q = 0; q < 4; q++) {
        int cc = (l + q * 32) * 4;
        float4 wf = *(const float4*)(w + cc);
        float4 bf = *(const float4*)(b + cc);
        v[q].x = v[q].x * rs * wf.x + bf.x;
        v[q].y = v[q].y * rs * wf.y + bf.y;
        v[q].z = v[q].z * rs * wf.z + bf.z;
        v[q].w = v[q].w * rs * wf.w + bf.w;
    }
}

template <int TWO>
__global__ void __launch_bounds__(256)
ln_kernel(const float* __restrict__ in, float* __restrict__ of,
          bf16* __restrict__ oh, bf16* __restrict__ ol,
          const float* __restrict__ w1, const float* __restrict__ b1,
          const float* __restrict__ w2, const float* __restrict__ b2)
{
    int row = blockIdx.x * 8 + (threadIdx.x >> 5);
    int l = threadIdx.x & 31;
    const float4* xr = (const float4*)(in + (size_t)row * 512);
    float4 v[4];
#pragma unroll
    for (int q = 0; q < 4; q++) v[q] = xr[l + q * 32];
    ln_stage(v, w1, b1, l);
    if (TWO) ln_stage(v, w2, b2, l);
#pragma unroll
    for (int q = 0; q < 4; q++) {
        size_t off = (size_t)row * 512 + (size_t)(l + q * 32) * 4;
        *(float4*)(of + off) = v[q];
        split4(v[q], oh + off, ol + off);
    }
}

// ---------------- prep kernels ----------------
__global__ void prep_scalars(const float* __restrict__ lam_re, const float* __restrict__ lam_im,
                             const float* __restrict__ log_step)
{
    int p = blockIdx.x * blockDim.x + threadIdx.x;
    if (p >= 512) return;
    float lr = lam_re[p], li = lam_im[p];
    float st = expf(log_step[p]);
    float er = expf(lr * st);
    float cc = er * cosf(li * st);
    float ss = er * sinf(li * st);
    g_lb[p] = make_float2(cc, ss);
    float ar = cc, ai = ss;
#pragma unroll
    for (int i = 0; i < 7; i++) {
        float nr = ar * ar - ai * ai, ni = 2.f * ar * ai;
        ar = nr; ai = ni;
    }
    g_lbN[p] = make_float2(ar, ai);
    float den = lr * lr + li * li;
    g_coef[p] = make_float2(((cc - 1.f) * lr + ss * li) / den, (ss * lr - (cc - 1.f) * li) / den);
}

__global__ void prep_wbar(const float* __restrict__ Bre, const float* __restrict__ Bim)
{
    int idx = blockIdx.x * 256 + threadIdx.x;
    if (idx >= 512 * 512) return;
    int p = idx >> 9, d = idx & 511;
    float2 cf = g_coef[p];
    float br = Bre[idx], bi = Bim[idx];
    split1(cf.x * br - cf.y * bi, &g_wbh[(size_t)p * 512 + d], &g_wbl[(size_t)p * 512 + d]);
    split1(cf.x * bi + cf.y * br, &g_wbh[(size_t)(512 + p) * 512 + d], &g_wbl[(size_t)(512 + p) * 512 + d]);
}

__global__ void prep_wc(const float* __restrict__ Cre, const float* __restrict__ Cim)
{
    int idx = blockIdx.x * 256 + threadIdx.x;
    if (idx >= 512 * 512) return;
    int d = idx >> 9, p = idx & 511;
    split1(2.f * Cre[idx], &g_wch[(size_t)d * 1024 + p], &g_wcl[(size_t)d * 1024 + p]);
    split1(-2.f * Cim[idx], &g_wch[(size_t)d * 1024 + 512 + p], &g_wcl[(size_t)d * 1024 + 512 + p]);
}

// interleave a/g rows: reordered row r: even -> a-row r/2, odd -> g-row 512 + r/2
__global__ void prep_ffe(const float* __restrict__ w)
{
    int idx = blockIdx.x * 256 + threadIdx.x;
    if (idx >= 1024 * 512) return;
    int r = idx >> 9, k = idx & 511;
    int src = (r & 1) ? (512 + (r >> 1)) : (r >> 1);
    split1(w[(size_t)src * 512 + k], &g_feh[(size_t)r * 512 + k], &g_fel[(size_t)r * 512 + k]);
}

__global__ void prep_ffd(const float* __restrict__ w)
{
    int idx = blockIdx.x * 256 + threadIdx.x;
    if (idx >= 512 * 512) return;
    split1(w[idx], &g_fdh[idx], &g_fdl[idx]);
}

__global__ void prep_enc(const float* __restrict__ w)   // (64,512) -> (512,64)
{
    int idx = blockIdx.x * 256 + threadIdx.x;
    if (idx >= 64 * 512) return;
    int k = idx >> 9, n = idx & 511;
    split1(w[idx], &g_weh[(size_t)n * 64 + k], &g_wel[(size_t)n * 64 + k]);
}

__global__ void cvx_kernel(const float* __restrict__ x)
{
    int idx = blockIdx.x * 256 + threadIdx.x;
    if (idx >= MR * 16) return;
    int mrow = idx >> 4, q = idx & 15;
    float4 v = *(const float4*)(x + (size_t)mrow * 64 + q * 4);
    size_t off = (size_t)mrow * 64 + (size_t)q * 4;
    split4(v, g_xbh + off, g_xbl + off);
}

// ---------------- chunked complex scan ----------------
__global__ void scan_pass1()
{
    const int p = threadIdx.x;
    const int c = blockIdx.x, b = blockIdx.y;
    float2 lb = g_lb[p];
    float xr = 0.f, xi = 0.f;
    const float* bu = g_big + ((size_t)(b * LSEQ + c * CLEN)) * 1024 + p;
    for (int t = 0; t < CLEN; t++) {
        float br = bu[0], bi = bu[512];
        float nr = fmaf(lb.x, xr, fmaf(-lb.y, xi, br));
        float ni = fmaf(lb.x, xi, fmaf(lb.y, xr, bi));
        xr = nr; xi = ni;
        bu += 1024;
    }
    g_carry[((size_t)b * NCHK + c) * 512 + p] = make_float2(xr, xi);
}

__global__ void scan_pass2()
{
    const int p = threadIdx.x;
    const int b = blockIdx.x;
    float2 A = g_lbN[p];
    float xr = 0.f, xi = 0.f;
#pragma unroll
    for (int c = 0; c < NCHK; c++) {
        size_t idx = ((size_t)b * NCHK + c) * 512 + p;
        float2 v = g_carry[idx];
        g_carry[idx] = make_float2(xr, xi);
        float nr = fmaf(A.x, xr, fmaf(-A.y, xi, v.x));
        float ni = fmaf(A.x, xi, fmaf(A.y, xr, v.y));
        xr = nr; xi = ni;
    }
}

__global__ void scan_pass3()
{
    const int p = threadIdx.x;
    const int c = blockIdx.x, b = blockIdx.y;
    float2 lb = g_lb[p];
    float2 cv = g_carry[((size_t)b * NCHK + c) * 512 + p];
    float xr = cv.x, xi = cv.y;
    size_t row0 = (size_t)(b * LSEQ + c * CLEN);
    const float* bu = g_big + row0 * 1024 + p;
    bf16* xh = g_xh + row0 * 1024 + p;
    bf16* xl = g_xl + row0 * 1024 + p;
    for (int t = 0; t < CLEN; t++) {
        float br = bu[0], bi = bu[512];
        float nr = fmaf(lb.x, xr, fmaf(-lb.y, xi, br));
        float ni = fmaf(lb.x, xi, fmaf(lb.y, xr, bi));
        xr = nr; xi = ni;
        split1(xr, xh, xl);
        split1(xi, xh + 512, xl + 512);
        bu += 1024; xh += 1024; xl += 1024;
    }
}

// ---------------- pool + head ----------------
__global__ void pool_head(const int* __restrict__ lengths,
                          const float* __restrict__ hw, const float* __restrict__ hb,
                          float* __restrict__ out)
{
    const int b = blockIdx.x;
    const int d = threadIdx.x;
    int len = lengths[b];
    const float* hp = g_h + ((size_t)b * LSEQ) * 512 + d;
    float s = 0.f;
    for (int t = 0; t < len; t++) s += hp[(size_t)t * 512];
    int den = len > 1 ? len : 1;
    float v = (s / (float)den) * hw[d];
    __shared__ float red[512];
    red[d] = v; __syncthreads();
    for (int st = 256; st > 0; st >>= 1) { if (d < st) red[d] += red[d + st]; __syncthreads(); }
    if (d == 0) out[b] = red[0] + hb[0];
}

// ---------------- launch ----------------
extern "C" void kernel_launch(void* const* d_in, const int* in_sizes, int n_in,
                              void* d_out, int out_size)
{
    const float* x       = (const float*)d_in[0];
    const int*   lengths = (const int*)  d_in[1];
    const float* enc_w   = (const float*)d_in[2];
    const float* enc_b   = (const float*)d_in[3];
    const float* lam_re  = (const float*)d_in[4];
    const float* lam_im  = (const float*)d_in[5];
    const float* Bre     = (const float*)d_in[6];
    const float* Bim     = (const float*)d_in[7];
    const float* Cre     = (const float*)d_in[8];
    const float* Cim     = (const float*)d_in[9];
    const float* Dp      = (const float*)d_in[10];
    const float* log_step= (const float*)d_in[11];
    const float* an_w    = (const float*)d_in[12];
    const float* an_b    = (const float*)d_in[13];
    const float* fn_w    = (const float*)d_in[14];
    const float* fn_b    = (const float*)d_in[15];
    const float* ffe_w   = (const float*)d_in[16];
    const float* ffd_w   = (const float*)d_in[17];
    const float* norm_w  = (const float*)d_in[18];
    const float* norm_b  = (const float*)d_in[19];
    const float* head_w  = (const float*)d_in[20];
    const float* head_b  = (const float*)d_in[21];
    float* out = (float*)d_out;

    cudaFuncSetAttribute(gemm_tc<0>, cudaFuncAttributeMaxDynamicSharedMemorySize, GSMEM);
    cudaFuncSetAttribute(gemm_tc<1>, cudaFuncAttributeMaxDynamicSharedMemorySize, GSMEM);
    cudaFuncSetAttribute(gemm_tc<2>, cudaFuncAttributeMaxDynamicSharedMemorySize, GSMEM);
    cudaFuncSetAttribute(gemm_tc<3>, cudaFuncAttributeMaxDynamicSharedMemorySize, GSMEM);
    cudaFuncSetAttribute(gemm_tc<4>, cudaFuncAttributeMaxDynamicSharedMemorySize, GSMEM);

    void *p_h, *p_b1, *p_b2, *p_big, *p_b1h, *p_b1l, *p_xh, *p_xl, *p_xbh, *p_xbl;
    void *p_wbh, *p_wbl, *p_wch, *p_wcl, *p_feh, *p_fel, *p_fdh, *p_fdl, *p_weh, *p_wel;
    cudaGetSymbolAddress(&p_h, g_h);     cudaGetSymbolAddress(&p_b1, g_b1);
    cudaGetSymbolAddress(&p_b2, g_b2);   cudaGetSymbolAddress(&p_big, g_big);
    cudaGetSymbolAddress(&p_b1h, g_b1h); cudaGetSymbolAddress(&p_b1l, g_b1l);
    cudaGetSymbolAddress(&p_xh, g_xh);   cudaGetSymbolAddress(&p_xl, g_xl);
    cudaGetSymbolAddress(&p_xbh, g_xbh); cudaGetSymbolAddress(&p_xbl, g_xbl);
    cudaGetSymbolAddress(&p_wbh, g_wbh); cudaGetSymbolAddress(&p_wbl, g_wbl);
    cudaGetSymbolAddress(&p_wch, g_wch); cudaGetSymbolAddress(&p_wcl, g_wcl);
    cudaGetSymbolAddress(&p_feh, g_feh); cudaGetSymbolAddress(&p_fel, g_fel);
    cudaGetSymbolAddress(&p_fdh, g_fdh); cudaGetSymbolAddress(&p_fdl, g_fdl);
    cudaGetSymbolAddress(&p_weh, g_weh); cudaGetSymbolAddress(&p_wel, g_wel);
    float* h   = (float*)p_h;  float* b1 = (float*)p_b1;
    float* b2  = (float*)p_b2; float* big = (float*)p_big;
    bf16* b1h = (bf16*)p_b1h; bf16* b1l = (bf16*)p_b1l;
    bf16* xh  = (bf16*)p_xh;  bf16* xl  = (bf16*)p_xl;
    bf16* xbh = (bf16*)p_xbh; bf16* xbl = (bf16*)p_xbl;
    bf16* wbh = (bf16*)p_wbh; bf16* wbl = (bf16*)p_wbl;
    bf16* wch = (bf16*)p_wch; bf16* wcl = (bf16*)p_wcl;
    bf16* feh = (bf16*)p_feh; bf16* fel = (bf16*)p_fel;
    bf16* fdh = (bf16*)p_fdh; bf16* fdl = (bf16*)p_fdl;
    bf16* weh = (bf16*)p_weh; bf16* wel = (bf16*)p_wel;

    // encoder: h = x @ enc_w + enc_b
    cvx_kernel<<<MR * 16 / 256, 256>>>(x);
    prep_enc<<<64 * 512 / 256, 256>>>(enc_w);
    gemm_tc<1><<<dim3(4, 256), 256, GSMEM>>>(xbh, xbl, 64, weh, wel, 64,
                                             h, 512, enc_b, nullptr, nullptr, nullptr);

    for (int i = 0; i < NLAYER; i++) {
        ln_kernel<1><<<MR / 8, 256>>>(h, b1, b1h, b1l,
                                      norm_w + i * 512, norm_b + i * 512,
                                      an_w + i * 512, an_b + i * 512);
        prep_scalars<<<2, 256>>>(lam_re + i * 512, lam_im + i * 512, log_step + i * 512);
        prep_wbar<<<512 * 512 / 256, 256>>>(Bre + (size_t)i * 512 * 512, Bim + (size_t)i * 512 * 512);
        prep_wc  <<<512 * 512 / 256, 256>>>(Cre + (size_t)i * 512 * 512, Cim + (size_t)i * 512 * 512);
        prep_ffe <<<1024 * 512 / 256, 256>>>(ffe_w + (size_t)i * 1024 * 512);
        prep_ffd <<<512 * 512 / 256, 256>>>(ffd_w + (size_t)i * 512 * 512);
        // Bu = fx @ Wbar^T -> big (re cols 0-511, im cols 512-1023)
        gemm_tc<0><<<dim3(8, 256), 256, GSMEM>>>(b1h, b1l, 512, wbh, wbl, 512,
                                                 big, 1024, nullptr, nullptr, nullptr, nullptr);
        // scan
        scan_pass1<<<dim3(NCHK, NBATCH), 512>>>();
        scan_pass2<<<NBATCH, 512>>>();
        scan_pass3<<<dim3(NCHK, NBATCH), 512>>>();
        // z = gelu(2Re(xs C^T) + Dp*fx) + fx
        gemm_tc<2><<<dim3(4, 256), 256, GSMEM>>>(xh, xl, 1024, wch, wcl, 1024,
                                                 b2, 512, Dp + i * 512, b1, nullptr, nullptr);
        // fx2 = LN(z)
        ln_kernel<0><<<MR / 8, 256>>>(b2, b1, b1h, b1l, fn_w + i * 512, fn_b + i * 512,
                                      nullptr, nullptr);
        // GEGLU fused: a*gelu(g) -> xh/xl (MR x 512)
        gemm_tc<4><<<dim3(8, 256), 256, GSMEM>>>(b1h, b1l, 512, feh, fel, 512,
                                                 nullptr, 512, nullptr, nullptr, xh, xl);
        // h += m @ ffd^T + fx2
        gemm_tc<3><<<dim3(4, 256), 256, GSMEM>>>(xh, xl, 512, fdh, fdl, 512,
                                                 h, 512, nullptr, b1, nullptr, nullptr);
    }

    pool_head<<<NBATCH, 512>>>(lengths, head_w, head_b, out);
}

// round 6
// speedup vs baseline: 2.1005x; 1.1538x over previous
#include <cuda_runtime.h>
#include <cuda_bf16.h>
#include <math.h>
#include <stdint.h>

#define MR 32768
#define LSEQ 4096
#define NBATCH 8
#define NLAYER 3
#define NCHK 32
#define CLEN 128

typedef __nv_bfloat16 bf16;

// ---------------- scratch ----------------
__device__ __align__(256) float g_h  [(size_t)MR * 512];
__device__ __align__(256) float g_b2 [(size_t)MR * 512];
__device__ __align__(256) float g_big[(size_t)MR * 1024];
__device__ __align__(256) bf16 g_b1h[(size_t)MR * 512];
__device__ __align__(256) bf16 g_b1l[(size_t)MR * 512];
__device__ __align__(256) bf16 g_xh [(size_t)MR * 1024];
__device__ __align__(256) bf16 g_xl [(size_t)MR * 1024];
__device__ __align__(256) bf16 g_xbh[(size_t)MR * 64];
__device__ __align__(256) bf16 g_xbl[(size_t)MR * 64];
__device__ __align__(256) bf16 g_wbh[1024 * 512];
__device__ __align__(256) bf16 g_wbl[1024 * 512];
__device__ __align__(256) bf16 g_wch[512 * 1024];
__device__ __align__(256) bf16 g_wcl[512 * 1024];
__device__ __align__(256) bf16 g_feh[1024 * 512];
__device__ __align__(256) bf16 g_fel[1024 * 512];
__device__ __align__(256) bf16 g_fdh[512 * 512];
__device__ __align__(256) bf16 g_fdl[512 * 512];
__device__ __align__(256) bf16 g_weh[512 * 64];
__device__ __align__(256) bf16 g_wel[512 * 64];
__device__ __align__(256) float2 g_lb[512];
__device__ __align__(256) float2 g_lbN[512];
__device__ __align__(256) float2 g_coef[512];
__device__ __align__(256) float2 g_carry[NBATCH * NCHK * 512];
__device__ __align__(256) float g_pool[NBATCH * NCHK * 512];

__device__ __forceinline__ float geluf(float x) {
    return 0.5f * x * (1.0f + erff(x * 0.70710678118654752f));
}
__device__ __forceinline__ uint32_t s2u(const void* p) {
    uint32_t a;
    asm("{ .reg .u64 t; cvta.to.shared.u64 t, %1; cvt.u32.u64 %0, t; }" : "=r"(a) : "l"(p));
    return a;
}
__device__ __forceinline__ void split1(float v, bf16* oh, bf16* ol) {
    bf16 h = __float2bfloat16(v);
    *oh = h;
    *ol = __float2bfloat16(v - __bfloat162float(h));
}
__device__ __forceinline__ void split4(float4 y, bf16* oh, bf16* ol) {
    union { bf16 b[4]; uint2 u; } H, L;
    float f[4] = {y.x, y.y, y.z, y.w};
#pragma unroll
    for (int e = 0; e < 4; e++) {
        bf16 h = __float2bfloat16(f[e]);
        H.b[e] = h;
        L.b[e] = __float2bfloat16(f[e] - __bfloat162float(h));
    }
    *(uint2*)oh = H.u;
    *(uint2*)ol = L.u;
}
__device__ __forceinline__ float2 rec2(const bf16* ph, const bf16* pl) {
    __nv_bfloat162 hh = *(const __nv_bfloat162*)ph;
    __nv_bfloat162 ll = *(const __nv_bfloat162*)pl;
    return make_float2(__bfloat162float(hh.x) + __bfloat162float(ll.x),
                       __bfloat162float(hh.y) + __bfloat162float(ll.y));
}

#define LDSM4(r0, r1, r2, r3, a) \
    asm volatile("ldmatrix.sync.aligned.m8n8.x4.shared.b16 {%0,%1,%2,%3}, [%4];" \
                 : "=r"(r0), "=r"(r1), "=r"(r2), "=r"(r3) : "r"(a))

#define MMA16816(c, a, b) \
    asm volatile("mma.sync.aligned.m16n8k16.row.col.f32.bf16.bf16.f32 " \
                 "{%0,%1,%2,%3}, {%4,%5,%6,%7}, {%8,%9}, {%0,%1,%2,%3};" \
                 : "+f"((c)[0]), "+f"((c)[1]), "+f"((c)[2]), "+f"((c)[3]) \
                 : "r"((a)[0]), "r"((a)[1]), "r"((a)[2]), "r"((a)[3]), \
                   "r"((b)[0]), "r"((b)[1]))

// ---------------- HMMA GEMM: 128x128 block, BK=64, 3-stage, 1 sync/chunk ----------
// smem stage: Ah/Al/Bh/Bl, each 128 rows x 144B pitch (128B data + 16B pad).
// EPI: 0 store fp32; 1 +vec; 2 gelu(acc+vec[n]*u)+u, u=mh+ml; 3 C+=acc+u; 4 GEGLU->hi/lo
#define PITCH 144
#define MATB (128 * PITCH)
#define STG (4 * MATB)
#define GSMEM (3 * STG)

template <int EPI>
__global__ void __launch_bounds__(256, 1)
gemm_tc(const bf16* __restrict__ Ah, const bf16* __restrict__ Al, int lda,
        const bf16* __restrict__ Wh, const bf16* __restrict__ Wl, int K,
        float* __restrict__ C, int ldc,
        const float* __restrict__ vec,
        const bf16* __restrict__ math, const bf16* __restrict__ matl,
        bf16* __restrict__ oh, bf16* __restrict__ ol)
{
    extern __shared__ char smembuf[];
    const uint32_t sb = s2u(smembuf);
    const int tid = threadIdx.x, lane = tid & 31, wid = tid >> 5;
    const int warpM = wid & 3, warpN = wid >> 2;
    const int bm = blockIdx.y << 7, bn = blockIdx.x << 7;
    const int NCH = K >> 6;

    float c[2][8][4];
#pragma unroll
    for (int i = 0; i < 2; i++)
#pragma unroll
        for (int j = 0; j < 8; j++)
#pragma unroll
            for (int q = 0; q < 4; q++) c[i][j][q] = 0.f;

    auto LOAD = [&](int ch) {
        if (ch < NCH) {
            uint32_t base = sb + (ch % 3) * STG;
            const bf16* gp[4] = {
                Ah + (size_t)bm * lda + ch * 64,
                Al + (size_t)bm * lda + ch * 64,
                Wh + (size_t)bn * K + ch * 64,
                Wl + (size_t)bn * K + ch * 64 };
            const int ld4[4] = {lda, lda, K, K};
#pragma unroll
            for (int mt = 0; mt < 4; mt++) {
                uint32_t mb = base + mt * MATB;
                const bf16* g = gp[mt];
                int ld = ld4[mt];
#pragma unroll
                for (int q = 0; q < 4; q++) {
                    int idx = tid + q * 256;
                    int row = idx >> 3, c16 = idx & 7;
                    uint32_t d = mb + row * PITCH + c16 * 16;
                    const bf16* src = g + (size_t)row * ld + c16 * 8;
                    asm volatile("cp.async.cg.shared.global [%0], [%1], 16;"
                                 :: "r"(d), "l"(src) : "memory");
                }
            }
        }
        asm volatile("cp.async.commit_group;" ::: "memory");
    };

    LOAD(0); LOAD(1);

    for (int ch = 0; ch < NCH; ch++) {
        asm volatile("cp.async.wait_group 1;" ::: "memory");
        __syncthreads();
        LOAD(ch + 2);

        uint32_t base = sb + (ch % 3) * STG;
#pragma unroll
        for (int kk = 0; kk < 4; kk++) {
            uint32_t kadd = kk * 32 + (lane >> 4) * 16;
            uint32_t ah[2][4], al[2][4], bh[8][2], bl[8][2];
#pragma unroll
            for (int mf = 0; mf < 2; mf++) {
                uint32_t row = warpM * 32 + mf * 16 + (lane & 15);
                uint32_t a0 = base + row * PITCH + kadd;
                LDSM4(ah[mf][0], ah[mf][1], ah[mf][2], ah[mf][3], a0);
                LDSM4(al[mf][0], al[mf][1], al[mf][2], al[mf][3], a0 + MATB);
            }
#pragma unroll
            for (int g = 0; g < 4; g++) {
                uint32_t row = warpN * 64 + g * 16 + (lane & 15);
                uint32_t a0 = base + 2 * MATB + row * PITCH + kadd;
                uint32_t r0, r1, r2, r3;
                LDSM4(r0, r1, r2, r3, a0);
                bh[2*g][0] = r0; bh[2*g][1] = r2;
                bh[2*g+1][0] = r1; bh[2*g+1][1] = r3;
                LDSM4(r0, r1, r2, r3, a0 + MATB);
                bl[2*g][0] = r0; bl[2*g][1] = r2;
                bl[2*g+1][0] = r1; bl[2*g+1][1] = r3;
            }
#pragma unroll
            for (int mf = 0; mf < 2; mf++)
#pragma unroll
                for (int jb = 0; jb < 8; jb++) {
                    MMA16816(c[mf][jb], ah[mf], bh[jb]);
                    MMA16816(c[mf][jb], ah[mf], bl[jb]);
                    MMA16816(c[mf][jb], al[mf], bh[jb]);
                }
        }
    }

    // ---------------- epilogue ----------------
#pragma unroll
    for (int mf = 0; mf < 2; mf++) {
        int m0 = bm + warpM * 32 + mf * 16 + (lane >> 2);
#pragma unroll
        for (int jb = 0; jb < 8; jb++) {
            int n = bn + warpN * 64 + jb * 8 + 2 * (lane & 3);
#pragma unroll
            for (int half = 0; half < 2; half++) {
                int r = m0 + half * 8;
                float v0 = c[mf][jb][2 * half], v1 = c[mf][jb][2 * half + 1];
                if (EPI == 4) {
                    int j = ((bn + warpN * 64 + jb * 8) >> 1) + (lane & 3);
                    size_t off = (size_t)r * 512 + j;
                    split1(v0 * geluf(v1), oh + off, ol + off);
                } else {
                    size_t off = (size_t)r * ldc + n;
                    if (EPI == 1) {
                        float2 bv = *(const float2*)(vec + n);
                        v0 += bv.x; v1 += bv.y;
                    } else if (EPI == 2) {
                        float2 u = rec2(math + (size_t)r * 512 + n, matl + (size_t)r * 512 + n);
                        float2 dv = *(const float2*)(vec + n);
                        v0 = geluf(v0 + dv.x * u.x) + u.x;
                        v1 = geluf(v1 + dv.y * u.y) + u.y;
                    } else if (EPI == 3) {
                        float2 u = rec2(math + (size_t)r * 512 + n, matl + (size_t)r * 512 + n);
                        float2 co = *(const float2*)(C + off);
                        v0 += co.x + u.x; v1 += co.y + u.y;
                    }
                    *(float2*)(C + off) = make_float2(v0, v1);
                }
            }
        }
    }
}

// ---------------- LayerNorm (warp per row; bf16 hi/lo output only) ----------------
__device__ __forceinline__ float wsum(float x) {
#pragma unroll
    for (int o = 16; o; o >>= 1) x += __shfl_xor_sync(0xFFFFFFFFu, x, o);
    return x;
}
__device__ __forceinline__ void ln_stage(float4 v[4], const float* __restrict__ w,
                                         const float* __restrict__ b, int l) {
    float s = 0.f;
#pragma unroll
    for (int q = 0; q < 4; q++) s += v[q].x + v[q].y + v[q].z + v[q].w;
    float mean = wsum(s) * (1.f / 512.f);
    float vv = 0.f;
#pragma unroll
    for (int q = 0; q < 4; q++) {
        v[q].x -= mean; v[q].y -= mean; v[q].z -= mean; v[q].w -= mean;
        vv += v[q].x * v[q].x + v[q].y * v[q].y + v[q].z * v[q].z + v[q].w * v[q].w;
    }
    float rs = rsqrtf(wsum(vv) * (1.f / 512.f) + 1e-5f);
#pragma unroll
    for (int q = 0; q < 4; q++) {
        int cc = (l + q * 32) * 4;
        float4 wf = *(const float4*)(w + cc);
        float4 bf = *(const float4*)(b + cc);
        v[q].x = v[q].x * rs * wf.x + bf.x;
        v[q].y = v[q].y * rs * wf.y + bf.y;
        v[q].z = v[q].z * rs * wf.z + bf.z;
        v[q].w = v[q].w * rs * wf.w + bf.w;
    }
}

template <int TWO>
__global__ void __launch_bounds__(256)
ln_kernel(const float* __restrict__ in,
          bf16* __restrict__ oh, bf16* __restrict__ ol,
          const float* __restrict__ w1, const float* __restrict__ b1,
          const float* __restrict__ w2, const float* __restrict__ b2)
{
    int row = blockIdx.x * 8 + (threadIdx.x >> 5);
    int l = threadIdx.x & 31;
    const float4* xr = (const float4*)(in + (size_t)row * 512);
    float4 v[4];
#pragma unroll
    for (int q = 0; q < 4; q++) v[q] = xr[l + q * 32];
    ln_stage(v, w1, b1, l);
    if (TWO) ln_stage(v, w2, b2, l);
#pragma unroll
    for (int q = 0; q < 4; q++) {
        size_t off = (size_t)row * 512 + (size_t)(l + q * 32) * 4;
        split4(v[q], oh + off, ol + off);
    }
}

// ---------------- prep kernels ----------------
__global__ void prep_scalars(const float* __restrict__ lam_re, const float* __restrict__ lam_im,
                             const float* __restrict__ log_step)
{
    int p = blockIdx.x * blockDim.x + threadIdx.x;
    if (p >= 512) return;
    float lr = lam_re[p], li = lam_im[p];
    float st = expf(log_step[p]);
    float er = expf(lr * st);
    float cc = er * cosf(li * st);
    float ss = er * sinf(li * st);
    g_lb[p] = make_float2(cc, ss);
    float ar = cc, ai = ss;
#pragma unroll
    for (int i = 0; i < 7; i++) {
        float nr = ar * ar - ai * ai, ni = 2.f * ar * ai;
        ar = nr; ai = ni;
    }
    g_lbN[p] = make_float2(ar, ai);
    float den = lr * lr + li * li;
    g_coef[p] = make_float2(((cc - 1.f) * lr + ss * li) / den, (ss * lr - (cc - 1.f) * li) / den);
}

__global__ void prep_wbar(const float* __restrict__ Bre, const float* __restrict__ Bim)
{
    int idx = blockIdx.x * 256 + threadIdx.x;
    if (idx >= 512 * 512) return;
    int p = idx >> 9, d = idx & 511;
    float2 cf = g_coef[p];
    float br = Bre[idx], bi = Bim[idx];
    split1(cf.x * br - cf.y * bi, &g_wbh[(size_t)p * 512 + d], &g_wbl[(size_t)p * 512 + d]);
    split1(cf.x * bi + cf.y * br, &g_wbh[(size_t)(512 + p) * 512 + d], &g_wbl[(size_t)(512 + p) * 512 + d]);
}

__global__ void prep_wc(const float* __restrict__ Cre, const float* __restrict__ Cim)
{
    int idx = blockIdx.x * 256 + threadIdx.x;
    if (idx >= 512 * 512) return;
    int d = idx >> 9, p = idx & 511;
    split1(2.f * Cre[idx], &g_wch[(size_t)d * 1024 + p], &g_wcl[(size_t)d * 1024 + p]);
    split1(-2.f * Cim[idx], &g_wch[(size_t)d * 1024 + 512 + p], &g_wcl[(size_t)d * 1024 + 512 + p]);
}

__global__ void prep_ffe(const float* __restrict__ w)
{
    int idx = blockIdx.x * 256 + threadIdx.x;
    if (idx >= 1024 * 512) return;
    int r = idx >> 9, k = idx & 511;
    int src = (r & 1) ? (512 + (r >> 1)) : (r >> 1);
    split1(w[(size_t)src * 512 + k], &g_feh[(size_t)r * 512 + k], &g_fel[(size_t)r * 512 + k]);
}

__global__ void prep_ffd(const float* __restrict__ w)
{
    int idx = blockIdx.x * 256 + threadIdx.x;
    if (idx >= 512 * 512) return;
    split1(w[idx], &g_fdh[idx], &g_fdl[idx]);
}

__global__ void prep_enc(const float* __restrict__ w)
{
    int idx = blockIdx.x * 256 + threadIdx.x;
    if (idx >= 64 * 512) return;
    int k = idx >> 9, n = idx & 511;
    split1(w[idx], &g_weh[(size_t)n * 64 + k], &g_wel[(size_t)n * 64 + k]);
}

__global__ void cvx_kernel(const float* __restrict__ x)
{
    int idx = blockIdx.x * 256 + threadIdx.x;
    if (idx >= MR * 16) return;
    int mrow = idx >> 4, q = idx & 15;
    float4 v = *(const float4*)(x + (size_t)mrow * 64 + q * 4);
    size_t off = (size_t)mrow * 64 + (size_t)q * 4;
    split4(v, g_xbh + off, g_xbl + off);
}

// ---------------- chunked complex scan ----------------
__global__ void scan_pass1()
{
    const int p = threadIdx.x;
    const int c = blockIdx.x, b = blockIdx.y;
    float2 lb = g_lb[p];
    float xr = 0.f, xi = 0.f;
    const float* bu = g_big + ((size_t)(b * LSEQ + c * CLEN)) * 1024 + p;
    for (int t = 0; t < CLEN; t++) {
        float br = bu[0], bi = bu[512];
        float nr = fmaf(lb.x, xr, fmaf(-lb.y, xi, br));
        float ni = fmaf(lb.x, xi, fmaf(lb.y, xr, bi));
        xr = nr; xi = ni;
        bu += 1024;
    }
    g_carry[((size_t)b * NCHK + c) * 512 + p] = make_float2(xr, xi);
}

__global__ void scan_pass2()
{
    const int p = threadIdx.x;
    const int b = blockIdx.x;
    float2 A = g_lbN[p];
    float xr = 0.f, xi = 0.f;
#pragma unroll
    for (int c = 0; c < NCHK; c++) {
        size_t idx = ((size_t)b * NCHK + c) * 512 + p;
        float2 v = g_carry[idx];
        g_carry[idx] = make_float2(xr, xi);
        float nr = fmaf(A.x, xr, fmaf(-A.y, xi, v.x));
        float ni = fmaf(A.x, xi, fmaf(A.y, xr, v.y));
        xr = nr; xi = ni;
    }
}

__global__ void scan_pass3()
{
    const int p = threadIdx.x;
    const int c = blockIdx.x, b = blockIdx.y;
    float2 lb = g_lb[p];
    float2 cv = g_carry[((size_t)b * NCHK + c) * 512 + p];
    float xr = cv.x, xi = cv.y;
    size_t row0 = (size_t)(b * LSEQ + c * CLEN);
    const float* bu = g_big + row0 * 1024 + p;
    bf16* xh = g_xh + row0 * 1024 + p;
    bf16* xl = g_xl + row0 * 1024 + p;
    for (int t = 0; t < CLEN; t++) {
        float br = bu[0], bi = bu[512];
        float nr = fmaf(lb.x, xr, fmaf(-lb.y, xi, br));
        float ni = fmaf(lb.x, xi, fmaf(lb.y, xr, bi));
        xr = nr; xi = ni;
        split1(xr, xh, xl);
        split1(xi, xh + 512, xl + 512);
        bu += 1024; xh += 1024; xl += 1024;
    }
}

// ---------------- pool (2-stage) + head ----------------
__global__ void pool_partial(const int* __restrict__ lengths)
{
    const int b = blockIdx.x, c = blockIdx.y;
    const int d = threadIdx.x;  // 512
    int len = lengths[b];
    int t0 = c * CLEN;
    int t1 = t0 + CLEN < len ? t0 + CLEN : len;
    float s = 0.f;
    const float* hp = g_h + ((size_t)(b * LSEQ + t0)) * 512 + d;
    for (int t = t0; t < t1; t++) { s += hp[0]; hp += 512; }
    g_pool[((size_t)b * NCHK + c) * 512 + d] = s;
}

__global__ void pool_head(const int* __restrict__ lengths,
                          const float* __restrict__ hw, const float* __restrict__ hb,
                          float* __restrict__ out)
{
    const int b = blockIdx.x;
    const int d = threadIdx.x;
    float s = 0.f;
#pragma unroll
    for (int c = 0; c < NCHK; c++) s += g_pool[((size_t)b * NCHK + c) * 512 + d];
    int len = lengths[b];
    int den = len > 1 ? len : 1;
    float v = (s / (float)den) * hw[d];
    __shared__ float red[512];
    red[d] = v; __syncthreads();
    for (int st = 256; st > 0; st >>= 1) { if (d < st) red[d] += red[d + st]; __syncthreads(); }
    if (d == 0) out[b] = red[0] + hb[0];
}

// ---------------- launch ----------------
extern "C" void kernel_launch(void* const* d_in, const int* in_sizes, int n_in,
                              void* d_out, int out_size)
{
    const float* x       = (const float*)d_in[0];
    const int*   lengths = (const int*)  d_in[1];
    const float* enc_w   = (const float*)d_in[2];
    const float* enc_b   = (const float*)d_in[3];
    const float* lam_re  = (const float*)d_in[4];
    const float* lam_im  = (const float*)d_in[5];
    const float* Bre     = (const float*)d_in[6];
    const float* Bim     = (const float*)d_in[7];
    const float* Cre     = (const float*)d_in[8];
    const float* Cim     = (const float*)d_in[9];
    const float* Dp      = (const float*)d_in[10];
    const float* log_step= (const float*)d_in[11];
    const float* an_w    = (const float*)d_in[12];
    const float* an_b    = (const float*)d_in[13];
    const float* fn_w    = (const float*)d_in[14];
    const float* fn_b    = (const float*)d_in[15];
    const float* ffe_w   = (const float*)d_in[16];
    const float* ffd_w   = (const float*)d_in[17];
    const float* norm_w  = (const float*)d_in[18];
    const float* norm_b  = (const float*)d_in[19];
    const float* head_w  = (const float*)d_in[20];
    const float* head_b  = (const float*)d_in[21];
    float* out = (float*)d_out;

    cudaFuncSetAttribute(gemm_tc<0>, cudaFuncAttributeMaxDynamicSharedMemorySize, GSMEM);
    cudaFuncSetAttribute(gemm_tc<1>, cudaFuncAttributeMaxDynamicSharedMemorySize, GSMEM);
    cudaFuncSetAttribute(gemm_tc<2>, cudaFuncAttributeMaxDynamicSharedMemorySize, GSMEM);
    cudaFuncSetAttribute(gemm_tc<3>, cudaFuncAttributeMaxDynamicSharedMemorySize, GSMEM);
    cudaFuncSetAttribute(gemm_tc<4>, cudaFuncAttributeMaxDynamicSharedMemorySize, GSMEM);

    void *p_h, *p_b2, *p_big, *p_b1h, *p_b1l, *p_xh, *p_xl, *p_xbh, *p_xbl;
    void *p_wbh, *p_wbl, *p_wch, *p_wcl, *p_feh, *p_fel, *p_fdh, *p_fdl, *p_weh, *p_wel;
    cudaGetSymbolAddress(&p_h, g_h);
    cudaGetSymbolAddress(&p_b2, g_b2);   cudaGetSymbolAddress(&p_big, g_big);
    cudaGetSymbolAddress(&p_b1h, g_b1h); cudaGetSymbolAddress(&p_b1l, g_b1l);
    cudaGetSymbolAddress(&p_xh, g_xh);   cudaGetSymbolAddress(&p_xl, g_xl);
    cudaGetSymbolAddress(&p_xbh, g_xbh); cudaGetSymbolAddress(&p_xbl, g_xbl);
    cudaGetSymbolAddress(&p_wbh, g_wbh); cudaGetSymbolAddress(&p_wbl, g_wbl);
    cudaGetSymbolAddress(&p_wch, g_wch); cudaGetSymbolAddress(&p_wcl, g_wcl);
    cudaGetSymbolAddress(&p_feh, g_feh); cudaGetSymbolAddress(&p_fel, g_fel);
    cudaGetSymbolAddress(&p_fdh, g_fdh); cudaGetSymbolAddress(&p_fdl, g_fdl);
    cudaGetSymbolAddress(&p_weh, g_weh); cudaGetSymbolAddress(&p_wel, g_wel);
    float* h   = (float*)p_h;
    float* b2  = (float*)p_b2; float* big = (float*)p_big;
    bf16* b1h = (bf16*)p_b1h; bf16* b1l = (bf16*)p_b1l;
    bf16* xh  = (bf16*)p_xh;  bf16* xl  = (bf16*)p_xl;
    bf16* xbh = (bf16*)p_xbh; bf16* xbl = (bf16*)p_xbl;
    bf16* wbh = (bf16*)p_wbh; bf16* wbl = (bf16*)p_wbl;
    bf16* wch = (bf16*)p_wch; bf16* wcl = (bf16*)p_wcl;
    bf16* feh = (bf16*)p_feh; bf16* fel = (bf16*)p_fel;
    bf16* fdh = (bf16*)p_fdh; bf16* fdl = (bf16*)p_fdl;
    bf16* weh = (bf16*)p_weh; bf16* wel = (bf16*)p_wel;

    // encoder: h = x @ enc_w + enc_b
    cvx_kernel<<<MR * 16 / 256, 256>>>(x);
    prep_enc<<<64 * 512 / 256, 256>>>(enc_w);
    gemm_tc<1><<<dim3(4, 256), 256, GSMEM>>>(xbh, xbl, 64, weh, wel, 64,
                                             h, 512, enc_b, nullptr, nullptr, nullptr, nullptr);

    for (int i = 0; i < NLAYER; i++) {
        ln_kernel<1><<<MR / 8, 256>>>(h, b1h, b1l,
                                      norm_w + i * 512, norm_b + i * 512,
                                      an_w + i * 512, an_b + i * 512);
        prep_scalars<<<2, 256>>>(lam_re + i * 512, lam_im + i * 512, log_step + i * 512);
        prep_wbar<<<512 * 512 / 256, 256>>>(Bre + (size_t)i * 512 * 512, Bim + (size_t)i * 512 * 512);
        prep_wc  <<<512 * 512 / 256, 256>>>(Cre + (size_t)i * 512 * 512, Cim + (size_t)i * 512 * 512);
        prep_ffe <<<1024 * 512 / 256, 256>>>(ffe_w + (size_t)i * 1024 * 512);
        prep_ffd <<<512 * 512 / 256, 256>>>(ffd_w + (size_t)i * 512 * 512);
        // Bu = fx @ Wbar^T -> big
        gemm_tc<0><<<dim3(8, 256), 256, GSMEM>>>(b1h, b1l, 512, wbh, wbl, 512,
                                                 big, 1024, nullptr, nullptr, nullptr, nullptr, nullptr);
        // scan
        scan_pass1<<<dim3(NCHK, NBATCH), 512>>>();
        scan_pass2<<<NBATCH, 512>>>();
        scan_pass3<<<dim3(NCHK, NBATCH), 512>>>();
        // z = gelu(2Re(xs C^T) + Dp*fx) + fx   (fx = b1h+b1l)
        gemm_tc<2><<<dim3(4, 256), 256, GSMEM>>>(xh, xl, 1024, wch, wcl, 1024,
                                                 b2, 512, Dp + i * 512, b1h, b1l, nullptr, nullptr);
        // fx2 = LN(z)
        ln_kernel<0><<<MR / 8, 256>>>(b2, b1h, b1l, fn_w + i * 512, fn_b + i * 512,
                                      nullptr, nullptr);
        // GEGLU fused: a*gelu(g) -> xh/xl
        gemm_tc<4><<<dim3(8, 256), 256, GSMEM>>>(b1h, b1l, 512, feh, fel, 512,
                                                 nullptr, 512, nullptr, nullptr, nullptr, xh, xl);
        // h += m @ ffd^T + fx2   (fx2 = b1h+b1l)
        gemm_tc<3><<<dim3(4, 256), 256, GSMEM>>>(xh, xl, 512, fdh, fdl, 512,
                                                 h, 512, nullptr, b1h, b1l, nullptr, nullptr);
    }

    pool_partial<<<dim3(NBATCH, NCHK), 512>>>(lengths);
    pool_head<<<NBATCH, 512>>>(lengths, head_w, head_b, out);
}

// round 7
// speedup vs baseline: 2.1096x; 1.0044x over previous
#include <cuda_runtime.h>
#include <cuda_bf16.h>
#include <math.h>
#include <stdint.h>

#define MR 32768
#define LSEQ 4096
#define NBATCH 8
#define NLAYER 3
#define NCHK 32
#define CLEN 128

typedef __nv_bfloat16 bf16;

// ---------------- scratch ----------------
__device__ __align__(256) float g_h  [(size_t)MR * 512];
__device__ __align__(256) float g_b2 [(size_t)MR * 512];
__device__ __align__(256) float g_big[(size_t)MR * 1024];
__device__ __align__(256) bf16 g_b1h[(size_t)MR * 512];
__device__ __align__(256) bf16 g_b1l[(size_t)MR * 512];
__device__ __align__(256) bf16 g_xh [(size_t)MR * 1024];
__device__ __align__(256) bf16 g_xl [(size_t)MR * 1024];
__device__ __align__(256) bf16 g_xbh[(size_t)MR * 64];
__device__ __align__(256) bf16 g_xbl[(size_t)MR * 64];
__device__ __align__(256) bf16 g_wbh[1024 * 512];
__device__ __align__(256) bf16 g_wbl[1024 * 512];
__device__ __align__(256) bf16 g_wch[512 * 1024];
__device__ __align__(256) bf16 g_wcl[512 * 1024];
__device__ __align__(256) bf16 g_feh[1024 * 512];
__device__ __align__(256) bf16 g_fel[1024 * 512];
__device__ __align__(256) bf16 g_fdh[512 * 512];
__device__ __align__(256) bf16 g_fdl[512 * 512];
__device__ __align__(256) bf16 g_weh[512 * 64];
__device__ __align__(256) bf16 g_wel[512 * 64];
__device__ __align__(256) float2 g_lb[512];
__device__ __align__(256) float2 g_lbN[512];
__device__ __align__(256) float2 g_coef[512];
__device__ __align__(256) float2 g_carry[NBATCH * NCHK * 512];
__device__ __align__(256) float g_pool[NBATCH * NCHK * 512];

__device__ __forceinline__ float geluf(float x) {
    return 0.5f * x * (1.0f + erff(x * 0.70710678118654752f));
}
__device__ __forceinline__ uint32_t s2u(const void* p) {
    uint32_t a;
    asm("{ .reg .u64 t; cvta.to.shared.u64 t, %1; cvt.u32.u64 %0, t; }" : "=r"(a) : "l"(p));
    return a;
}
__device__ __forceinline__ void split1(float v, bf16* oh, bf16* ol) {
    bf16 h = __float2bfloat16(v);
    *oh = h;
    *ol = __float2bfloat16(v - __bfloat162float(h));
}
__device__ __forceinline__ uint32_t pack2(bf16 a, bf16 b) {
    union { bf16 h[2]; uint32_t u; } u;
    u.h[0] = a; u.h[1] = b;
    return u.u;
}
__device__ __forceinline__ void split4(float4 y, bf16* oh, bf16* ol) {
    union { bf16 b[4]; uint2 u; } H, L;
    float f[4] = {y.x, y.y, y.z, y.w};
#pragma unroll
    for (int e = 0; e < 4; e++) {
        bf16 h = __float2bfloat16(f[e]);
        H.b[e] = h;
        L.b[e] = __float2bfloat16(f[e] - __bfloat162float(h));
    }
    *(uint2*)oh = H.u;
    *(uint2*)ol = L.u;
}
__device__ __forceinline__ float2 rec2(const bf16* ph, const bf16* pl) {
    __nv_bfloat162 hh = *(const __nv_bfloat162*)ph;
    __nv_bfloat162 ll = *(const __nv_bfloat162*)pl;
    return make_float2(__bfloat162float(hh.x) + __bfloat162float(ll.x),
                       __bfloat162float(hh.y) + __bfloat162float(ll.y));
}

#define LDSM4(r0, r1, r2, r3, a) \
    asm volatile("ldmatrix.sync.aligned.m8n8.x4.shared.b16 {%0,%1,%2,%3}, [%4];" \
                 : "=r"(r0), "=r"(r1), "=r"(r2), "=r"(r3) : "r"(a))

#define MMA16816(c, a, b) \
    asm volatile("mma.sync.aligned.m16n8k16.row.col.f32.bf16.bf16.f32 " \
                 "{%0,%1,%2,%3}, {%4,%5,%6,%7}, {%8,%9}, {%0,%1,%2,%3};" \
                 : "+f"((c)[0]), "+f"((c)[1]), "+f"((c)[2]), "+f"((c)[3]) \
                 : "r"((a)[0]), "r"((a)[1]), "r"((a)[2]), "r"((a)[3]), \
                   "r"((b)[0]), "r"((b)[1]))

// ---------------- HMMA GEMM: 128x128 block, BK=64, 3-stage ----------
// EPI: 1 +vec store fp32; 2 gelu(acc+vec[n]*u)+u (u=mh+ml); 3 C+=acc+u; 4 GEGLU->hi/lo;
//      5 local complex scan over 128-row chunk -> g_big (interleaved re/im) + carry
#define PITCH 144
#define MATB (128 * PITCH)
#define STG (4 * MATB)
#define GSMEM (3 * STG)

template <int EPI>
__global__ void __launch_bounds__(256, 1)
gemm_tc(const bf16* __restrict__ Ah, const bf16* __restrict__ Al, int lda,
        const bf16* __restrict__ Wh, const bf16* __restrict__ Wl, int K,
        float* __restrict__ C, int ldc,
        const float* __restrict__ vec,
        const bf16* __restrict__ math, const bf16* __restrict__ matl,
        bf16* __restrict__ oh, bf16* __restrict__ ol)
{
    extern __shared__ char smembuf[];
    const uint32_t sb = s2u(smembuf);
    const int tid = threadIdx.x, lane = tid & 31, wid = tid >> 5;
    const int warpM = wid & 3, warpN = wid >> 2;
    const int bm = blockIdx.y << 7, bn = blockIdx.x << 7;
    const int NCH = K >> 6;

    float c[2][8][4];
#pragma unroll
    for (int i = 0; i < 2; i++)
#pragma unroll
        for (int j = 0; j < 8; j++)
#pragma unroll
            for (int q = 0; q < 4; q++) c[i][j][q] = 0.f;

    auto LOAD = [&](int ch) {
        if (ch < NCH) {
            uint32_t base = sb + (ch % 3) * STG;
            const bf16* gp[4] = {
                Ah + (size_t)bm * lda + ch * 64,
                Al + (size_t)bm * lda + ch * 64,
                Wh + (size_t)bn * K + ch * 64,
                Wl + (size_t)bn * K + ch * 64 };
            const int ld4[4] = {lda, lda, K, K};
#pragma unroll
            for (int mt = 0; mt < 4; mt++) {
                uint32_t mb = base + mt * MATB;
                const bf16* g = gp[mt];
                int ld = ld4[mt];
#pragma unroll
                for (int q = 0; q < 4; q++) {
                    int idx = tid + q * 256;
                    int row = idx >> 3, c16 = idx & 7;
                    uint32_t d = mb + row * PITCH + c16 * 16;
                    const bf16* src = g + (size_t)row * ld + c16 * 8;
                    asm volatile("cp.async.cg.shared.global [%0], [%1], 16;"
                                 :: "r"(d), "l"(src) : "memory");
                }
            }
        }
        asm volatile("cp.async.commit_group;" ::: "memory");
    };

    LOAD(0); LOAD(1);

    for (int ch = 0; ch < NCH; ch++) {
        asm volatile("cp.async.wait_group 1;" ::: "memory");
        __syncthreads();
        LOAD(ch + 2);

        uint32_t base = sb + (ch % 3) * STG;
#pragma unroll
        for (int kk = 0; kk < 4; kk++) {
            uint32_t kadd = kk * 32 + (lane >> 4) * 16;
            uint32_t ah[2][4], al[2][4], bh[8][2], bl[8][2];
#pragma unroll
            for (int mf = 0; mf < 2; mf++) {
                uint32_t row = warpM * 32 + mf * 16 + (lane & 15);
                uint32_t a0 = base + row * PITCH + kadd;
                LDSM4(ah[mf][0], ah[mf][1], ah[mf][2], ah[mf][3], a0);
                LDSM4(al[mf][0], al[mf][1], al[mf][2], al[mf][3], a0 + MATB);
            }
#pragma unroll
            for (int g = 0; g < 4; g++) {
                uint32_t row = warpN * 64 + g * 16 + (lane & 15);
                uint32_t a0 = base + 2 * MATB + row * PITCH + kadd;
                uint32_t r0, r1, r2, r3;
                LDSM4(r0, r1, r2, r3, a0);
                bh[2*g][0] = r0; bh[2*g][1] = r2;
                bh[2*g+1][0] = r1; bh[2*g+1][1] = r3;
                LDSM4(r0, r1, r2, r3, a0 + MATB);
                bl[2*g][0] = r0; bl[2*g][1] = r2;
                bl[2*g+1][0] = r1; bl[2*g+1][1] = r3;
            }
            // term-outer, jb-inner: 8 independent MMAs between accumulator reuse
#pragma unroll
            for (int mf = 0; mf < 2; mf++) {
#pragma unroll
                for (int jb = 0; jb < 8; jb++) MMA16816(c[mf][jb], ah[mf], bh[jb]);
#pragma unroll
                for (int jb = 0; jb < 8; jb++) MMA16816(c[mf][jb], ah[mf], bl[jb]);
#pragma unroll
                for (int jb = 0; jb < 8; jb++) MMA16816(c[mf][jb], al[mf], bh[jb]);
            }
        }
    }

    if (EPI == 5) {
        // dump acc to smem scratch, then 64 threads scan complex column pairs
        float* sc = (float*)smembuf;
        __syncthreads();
#pragma unroll
        for (int mf = 0; mf < 2; mf++) {
            int r0 = warpM * 32 + mf * 16 + (lane >> 2);
#pragma unroll
            for (int jb = 0; jb < 8; jb++) {
                int n = warpN * 64 + jb * 8 + 2 * (lane & 3);
#pragma unroll
                for (int half = 0; half < 2; half++) {
                    *(float2*)&sc[(r0 + half * 8) * 128 + n] =
                        make_float2(c[mf][jb][2 * half], c[mf][jb][2 * half + 1]);
                }
            }
        }
        __syncthreads();
        if (tid < 64) {
            int j = tid;
            int pglob = (bn >> 1) + j;
            float2 lb = g_lb[pglob];
            float xr = 0.f, xi = 0.f;
            float* outp = g_big + (size_t)bm * 1024 + bn + 2 * j;
#pragma unroll 4
            for (int t = 0; t < CLEN; t++) {
                float2 bu = *(float2*)&sc[t * 128 + 2 * j];
                float nr = fmaf(lb.x, xr, fmaf(-lb.y, xi, bu.x));
                float ni = fmaf(lb.x, xi, fmaf(lb.y, xr, bu.y));
                xr = nr; xi = ni;
                *(float2*)(outp + (size_t)t * 1024) = make_float2(xr, xi);
            }
            int b = bm >> 12, cch = (bm >> 7) & 31;
            g_carry[((size_t)b * NCHK + cch) * 512 + pglob] = make_float2(xr, xi);
        }
        return;
    }

    // ---------------- standard epilogues ----------------
#pragma unroll
    for (int mf = 0; mf < 2; mf++) {
        int m0 = bm + warpM * 32 + mf * 16 + (lane >> 2);
#pragma unroll
        for (int jb = 0; jb < 8; jb++) {
            int n = bn + warpN * 64 + jb * 8 + 2 * (lane & 3);
#pragma unroll
            for (int half = 0; half < 2; half++) {
                int r = m0 + half * 8;
                float v0 = c[mf][jb][2 * half], v1 = c[mf][jb][2 * half + 1];
                if (EPI == 4) {
                    int j = ((bn + warpN * 64 + jb * 8) >> 1) + (lane & 3);
                    size_t off = (size_t)r * 512 + j;
                    split1(v0 * geluf(v1), oh + off, ol + off);
                } else {
                    size_t off = (size_t)r * ldc + n;
                    if (EPI == 1) {
                        float2 bv = *(const float2*)(vec + n);
                        v0 += bv.x; v1 += bv.y;
                    } else if (EPI == 2) {
                        float2 u = rec2(math + (size_t)r * 512 + n, matl + (size_t)r * 512 + n);
                        float2 dv = *(const float2*)(vec + n);
                        v0 = geluf(v0 + dv.x * u.x) + u.x;
                        v1 = geluf(v1 + dv.y * u.y) + u.y;
                    } else if (EPI == 3) {
                        float2 u = rec2(math + (size_t)r * 512 + n, matl + (size_t)r * 512 + n);
                        float2 co = *(const float2*)(C + off);
                        v0 += co.x + u.x; v1 += co.y + u.y;
                    }
                    *(float2*)(C + off) = make_float2(v0, v1);
                }
            }
        }
    }
}

// ---------------- LayerNorm (warp per row) ----------------
__device__ __forceinline__ float wsum(float x) {
#pragma unroll
    for (int o = 16; o; o >>= 1) x += __shfl_xor_sync(0xFFFFFFFFu, x, o);
    return x;
}
__device__ __forceinline__ void ln_stage(float4 v[4], const float* __restrict__ w,
                                         const float* __restrict__ b, int l) {
    float s = 0.f;
#pragma unroll
    for (int q = 0; q < 4; q++) s += v[q].x + v[q].y + v[q].z + v[q].w;
    float mean = wsum(s) * (1.f / 512.f);
    float vv = 0.f;
#pragma unroll
    for (int q = 0; q < 4; q++) {
        v[q].x -= mean; v[q].y -= mean; v[q].z -= mean; v[q].w -= mean;
        vv += v[q].x * v[q].x + v[q].y * v[q].y + v[q].z * v[q].z + v[q].w * v[q].w;
    }
    float rs = rsqrtf(wsum(vv) * (1.f / 512.f) + 1e-5f);
#pragma unroll
    for (int q = 0; q < 4; q++) {
        int cc = (l + q * 32) * 4;
        float4 wf = *(const float4*)(w + cc);
        float4 bf = *(const float4*)(b + cc);
        v[q].x = v[q].x * rs * wf.x + bf.x;
        v[q].y = v[q].y * rs * wf.y + bf.y;
        v[q].z = v[q].z * rs * wf.z + bf.z;
        v[q].w = v[q].w * rs * wf.w + bf.w;
    }
}

template <int TWO>
__global__ void __launch_bounds__(256)
ln_kernel(const float* __restrict__ in,
          bf16* __restrict__ oh, bf16* __restrict__ ol,
          const float* __restrict__ w1, const float* __restrict__ b1,
          const float* __restrict__ w2, const float* __restrict__ b2)
{
    int row = blockIdx.x * 8 + (threadIdx.x >> 5);
    int l = threadIdx.x & 31;
    const float4* xr = (const float4*)(in + (size_t)row * 512);
    float4 v[4];
#pragma unroll
    for (int q = 0; q < 4; q++) v[q] = xr[l + q * 32];
    ln_stage(v, w1, b1, l);
    if (TWO) ln_stage(v, w2, b2, l);
#pragma unroll
    for (int q = 0; q < 4; q++) {
        size_t off = (size_t)row * 512 + (size_t)(l + q * 32) * 4;
        split4(v[q], oh + off, ol + off);
    }
}

// ---------------- prep kernels ----------------
__global__ void prep_scalars(const float* __restrict__ lam_re, const float* __restrict__ lam_im,
                             const float* __restrict__ log_step)
{
    int p = blockIdx.x * blockDim.x + threadIdx.x;
    if (p >= 512) return;
    float lr = lam_re[p], li = lam_im[p];
    float st = expf(log_step[p]);
    float er = expf(lr * st);
    float cc = er * cosf(li * st);
    float ss = er * sinf(li * st);
    g_lb[p] = make_float2(cc, ss);
    float ar = cc, ai = ss;
#pragma unroll
    for (int i = 0; i < 7; i++) {
        float nr = ar * ar - ai * ai, ni = 2.f * ar * ai;
        ar = nr; ai = ni;
    }
    g_lbN[p] = make_float2(ar, ai);
    float den = lr * lr + li * li;
    g_coef[p] = make_float2(((cc - 1.f) * lr + ss * li) / den, (ss * lr - (cc - 1.f) * li) / den);
}

// interleaved: Wbar rows 2p (re), 2p+1 (im)
__global__ void prep_wbar(const float* __restrict__ Bre, const float* __restrict__ Bim)
{
    int idx = blockIdx.x * 256 + threadIdx.x;
    if (idx >= 512 * 512) return;
    int p = idx >> 9, d = idx & 511;
    float2 cf = g_coef[p];
    float br = Bre[idx], bi = Bim[idx];
    split1(cf.x * br - cf.y * bi, &g_wbh[(size_t)(2 * p) * 512 + d], &g_wbl[(size_t)(2 * p) * 512 + d]);
    split1(cf.x * bi + cf.y * br, &g_wbh[(size_t)(2 * p + 1) * 512 + d], &g_wbl[(size_t)(2 * p + 1) * 512 + d]);
}

// interleaved K: wc[d][2p]=2Cre, wc[d][2p+1]=-2Cim
__global__ void prep_wc(const float* __restrict__ Cre, const float* __restrict__ Cim)
{
    int idx = blockIdx.x * 256 + threadIdx.x;
    if (idx >= 512 * 512) return;
    int d = idx >> 9, p = idx & 511;
    split1(2.f * Cre[idx], &g_wch[(size_t)d * 1024 + 2 * p], &g_wcl[(size_t)d * 1024 + 2 * p]);
    split1(-2.f * Cim[idx], &g_wch[(size_t)d * 1024 + 2 * p + 1], &g_wcl[(size_t)d * 1024 + 2 * p + 1]);
}

__global__ void prep_ffe(const float* __restrict__ w)
{
    int idx = blockIdx.x * 256 + threadIdx.x;
    if (idx >= 1024 * 512) return;
    int r = idx >> 9, k = idx & 511;
    int src = (r & 1) ? (512 + (r >> 1)) : (r >> 1);
    split1(w[(size_t)src * 512 + k], &g_feh[(size_t)r * 512 + k], &g_fel[(size_t)r * 512 + k]);
}

__global__ void prep_ffd(const float* __restrict__ w)
{
    int idx = blockIdx.x * 256 + threadIdx.x;
    if (idx >= 512 * 512) return;
    split1(w[idx], &g_fdh[idx], &g_fdl[idx]);
}

__global__ void prep_enc(const float* __restrict__ w)
{
    int idx = blockIdx.x * 256 + threadIdx.x;
    if (idx >= 64 * 512) return;
    int k = idx >> 9, n = idx & 511;
    split1(w[idx], &g_weh[(size_t)n * 64 + k], &g_wel[(size_t)n * 64 + k]);
}

__global__ void cvx_kernel(const float* __restrict__ x)
{
    int idx = blockIdx.x * 256 + threadIdx.x;
    if (idx >= MR * 16) return;
    int mrow = idx >> 4, q = idx & 15;
    float4 v = *(const float4*)(x + (size_t)mrow * 64 + q * 4);
    size_t off = (size_t)mrow * 64 + (size_t)q * 4;
    split4(v, g_xbh + off, g_xbl + off);
}

// ---------------- scan combine (pass1 now fused into Bu GEMM) ----------------
__global__ void scan_pass2()
{
    const int p = threadIdx.x;
    const int b = blockIdx.x;
    float2 A = g_lbN[p];
    float xr = 0.f, xi = 0.f;
#pragma unroll
    for (int c = 0; c < NCHK; c++) {
        size_t idx = ((size_t)b * NCHK + c) * 512 + p;
        float2 v = g_carry[idx];
        g_carry[idx] = make_float2(xr, xi);
        float nr = fmaf(A.x, xr, fmaf(-A.y, xi, v.x));
        float ni = fmaf(A.x, xi, fmaf(A.y, xr, v.y));
        xr = nr; xi = ni;
    }
}

// x_t = local_t + lb^(t+1) * carry ; write bf16 hi/lo interleaved
__global__ void scan_pass3()
{
    const int p = threadIdx.x;   // 512
    const int c = blockIdx.x, b = blockIdx.y;
    float2 lb = g_lb[p];
    float2 cv = g_carry[((size_t)b * NCHK + c) * 512 + p];
    float pr = lb.x, pi = lb.y;
    size_t row0 = (size_t)(b * LSEQ + c * CLEN);
    const float2* loc = (const float2*)(g_big + row0 * 1024) + p;
    uint32_t* xh = (uint32_t*)(g_xh + row0 * 1024) + p;
    uint32_t* xl = (uint32_t*)(g_xl + row0 * 1024) + p;
    for (int t = 0; t < CLEN; t++) {
        float2 l = loc[(size_t)t * 512];
        float xr = fmaf(pr, cv.x, fmaf(-pi, cv.y, l.x));
        float xi = fmaf(pr, cv.y, fmaf(pi, cv.x, l.y));
        float nr = pr * lb.x - pi * lb.y;
        pi = pr * lb.y + pi * lb.x; pr = nr;
        bf16 hr = __float2bfloat16(xr);
        bf16 hi2 = __float2bfloat16(xi);
        xh[(size_t)t * 512] = pack2(hr, hi2);
        xl[(size_t)t * 512] = pack2(__float2bfloat16(xr - __bfloat162float(hr)),
                                    __float2bfloat16(xi - __bfloat162float(hi2)));
    }
}

// ---------------- pool (2-stage) + head ----------------
__global__ void pool_partial(const int* __restrict__ lengths)
{
    const int b = blockIdx.x, c = blockIdx.y;
    const int d = threadIdx.x;
    int len = lengths[b];
    int t0 = c * CLEN;
    int t1 = t0 + CLEN < len ? t0 + CLEN : len;
    float s = 0.f;
    const float* hp = g_h + ((size_t)(b * LSEQ + t0)) * 512 + d;
    for (int t = t0; t < t1; t++) { s += hp[0]; hp += 512; }
    g_pool[((size_t)b * NCHK + c) * 512 + d] = s;
}

__global__ void pool_head(const int* __restrict__ lengths,
                          const float* __restrict__ hw, const float* __restrict__ hb,
                          float* __restrict__ out)
{
    const int b = blockIdx.x;
    const int d = threadIdx.x;
    float s = 0.f;
#pragma unroll
    for (int c = 0; c < NCHK; c++) s += g_pool[((size_t)b * NCHK + c) * 512 + d];
    int len = lengths[b];
    int den = len > 1 ? len : 1;
    float v = (s / (float)den) * hw[d];
    __shared__ float red[512];
    red[d] = v; __syncthreads();
    for (int st = 256; st > 0; st >>= 1) { if (d < st) red[d] += red[d + st]; __syncthreads(); }
    if (d == 0) out[b] = red[0] + hb[0];
}

// ---------------- launch ----------------
extern "C" void kernel_launch(void* const* d_in, const int* in_sizes, int n_in,
                              void* d_out, int out_size)
{
    const float* x       = (const float*)d_in[0];
    const int*   lengths = (const int*)  d_in[1];
    const float* enc_w   = (const float*)d_in[2];
    const float* enc_b   = (const float*)d_in[3];
    const float* lam_re  = (const float*)d_in[4];
    const float* lam_im  = (const float*)d_in[5];
    const float* Bre     = (const float*)d_in[6];
    const float* Bim     = (const float*)d_in[7];
    const float* Cre     = (const float*)d_in[8];
    const float* Cim     = (const float*)d_in[9];
    const float* Dp      = (const float*)d_in[10];
    const float* log_step= (const float*)d_in[11];
    const float* an_w    = (const float*)d_in[12];
    const float* an_b    = (const float*)d_in[13];
    const float* fn_w    = (const float*)d_in[14];
    const float* fn_b    = (const float*)d_in[15];
    const float* ffe_w   = (const float*)d_in[16];
    const float* ffd_w   = (const float*)d_in[17];
    const float* norm_w  = (const float*)d_in[18];
    const float* norm_b  = (const float*)d_in[19];
    const float* head_w  = (const float*)d_in[20];
    const float* head_b  = (const float*)d_in[21];
    float* out = (float*)d_out;

    cudaFuncSetAttribute(gemm_tc<1>, cudaFuncAttributeMaxDynamicSharedMemorySize, GSMEM);
    cudaFuncSetAttribute(gemm_tc<2>, cudaFuncAttributeMaxDynamicSharedMemorySize, GSMEM);
    cudaFuncSetAttribute(gemm_tc<3>, cudaFuncAttributeMaxDynamicSharedMemorySize, GSMEM);
    cudaFuncSetAttribute(gemm_tc<4>, cudaFuncAttributeMaxDynamicSharedMemorySize, GSMEM);
    cudaFuncSetAttribute(gemm_tc<5>, cudaFuncAttributeMaxDynamicSharedMemorySize, GSMEM);

    void *p_h, *p_b2, *p_big, *p_b1h, *p_b1l, *p_xh, *p_xl, *p_xbh, *p_xbl;
    void *p_wbh, *p_wbl, *p_wch, *p_wcl, *p_feh, *p_fel, *p_fdh, *p_fdl, *p_weh, *p_wel;
    cudaGetSymbolAddress(&p_h, g_h);
    cudaGetSymbolAddress(&p_b2, g_b2);   cudaGetSymbolAddress(&p_big, g_big);
    cudaGetSymbolAddress(&p_b1h, g_b1h); cudaGetSymbolAddress(&p_b1l, g_b1l);
    cudaGetSymbolAddress(&p_xh, g_xh);   cudaGetSymbolAddress(&p_xl, g_xl);
    cudaGetSymbolAddress(&p_xbh, g_xbh); cudaGetSymbolAddress(&p_xbl, g_xbl);
    cudaGetSymbolAddress(&p_wbh, g_wbh); cudaGetSymbolAddress(&p_wbl, g_wbl);
    cudaGetSymbolAddress(&p_wch, g_wch); cudaGetSymbolAddress(&p_wcl, g_wcl);
    cudaGetSymbolAddress(&p_feh, g_feh); cudaGetSymbolAddress(&p_fel, g_fel);
    cudaGetSymbolAddress(&p_fdh, g_fdh); cudaGetSymbolAddress(&p_fdl, g_fdl);
    cudaGetSymbolAddress(&p_weh, g_weh); cudaGetSymbolAddress(&p_wel, g_wel);
    float* h   = (float*)p_h;
    float* b2  = (float*)p_b2; float* big = (float*)p_big;
    bf16* b1h = (bf16*)p_b1h; bf16* b1l = (bf16*)p_b1l;
    bf16* xh  = (bf16*)p_xh;  bf16* xl  = (bf16*)p_xl;
    bf16* xbh = (bf16*)p_xbh; bf16* xbl = (bf16*)p_xbl;
    bf16* wbh = (bf16*)p_wbh; bf16* wbl = (bf16*)p_wbl;
    bf16* wch = (bf16*)p_wch; bf16* wcl = (bf16*)p_wcl;
    bf16* feh = (bf16*)p_feh; bf16* fel = (bf16*)p_fel;
    bf16* fdh = (bf16*)p_fdh; bf16* fdl = (bf16*)p_fdl;
    bf16* weh = (bf16*)p_weh; bf16* wel = (bf16*)p_wel;

    // encoder: h = x @ enc_w + enc_b
    cvx_kernel<<<MR * 16 / 256, 256>>>(x);
    prep_enc<<<64 * 512 / 256, 256>>>(enc_w);
    gemm_tc<1><<<dim3(4, 256), 256, GSMEM>>>(xbh, xbl, 64, weh, wel, 64,
                                             h, 512, enc_b, nullptr, nullptr, nullptr, nullptr);

    for (int i = 0; i < NLAYER; i++) {
        ln_kernel<1><<<MR / 8, 256>>>(h, b1h, b1l,
                                      norm_w + i * 512, norm_b + i * 512,
                                      an_w + i * 512, an_b + i * 512);
        prep_scalars<<<2, 256>>>(lam_re + i * 512, lam_im + i * 512, log_step + i * 512);
        prep_wbar<<<512 * 512 / 256, 256>>>(Bre + (size_t)i * 512 * 512, Bim + (size_t)i * 512 * 512);
        prep_wc  <<<512 * 512 / 256, 256>>>(Cre + (size_t)i * 512 * 512, Cim + (size_t)i * 512 * 512);
        prep_ffe <<<1024 * 512 / 256, 256>>>(ffe_w + (size_t)i * 1024 * 512);
        prep_ffd <<<512 * 512 / 256, 256>>>(ffd_w + (size_t)i * 512 * 512);
        // Bu GEMM + fused chunk-local scan -> g_big (local) + g_carry
        gemm_tc<5><<<dim3(8, 256), 256, GSMEM>>>(b1h, b1l, 512, wbh, wbl, 512,
                                                 big, 1024, nullptr, nullptr, nullptr, nullptr, nullptr);
        scan_pass2<<<NBATCH, 512>>>();
        scan_pass3<<<dim3(NCHK, NBATCH), 512>>>();
        // z = gelu(2Re(xs C^T) + Dp*fx) + fx
        gemm_tc<2><<<dim3(4, 256), 256, GSMEM>>>(xh, xl, 1024, wch, wcl, 1024,
                                                 b2, 512, Dp + i * 512, b1h, b1l, nullptr, nullptr);
        // fx2 = LN(z)
        ln_kernel<0><<<MR / 8, 256>>>(b2, b1h, b1l, fn_w + i * 512, fn_b + i * 512,
                                      nullptr, nullptr);
        // GEGLU fused: a*gelu(g) -> xh/xl
        gemm_tc<4><<<dim3(8, 256), 256, GSMEM>>>(b1h, b1l, 512, feh, fel, 512,
                                                 nullptr, 512, nullptr, nullptr, nullptr, xh, xl);
        // h += m @ ffd^T + fx2
        gemm_tc<3><<<dim3(4, 256), 256, GSMEM>>>(xh, xl, 512, fdh, fdl, 512,
                                                 h, 512, nullptr, b1h, b1l, nullptr, nullptr);
    }

    pool_partial<<<dim3(NBATCH, NCHK), 512>>>(lengths);
    pool_head<<<NBATCH, 512>>>(lengths, head_w, head_b, out);
}

// round 9
// speedup vs baseline: 2.4657x; 1.1688x over previous
#include <cuda_runtime.h>
#include <cuda_bf16.h>
#include <math.h>
#include <stdint.h>

#define MR 32768
#define LSEQ 4096
#define NBATCH 8
#define NLAYER 3
#define NCHK 32
#define CLEN 128

typedef __nv_bfloat16 bf16;

// ---------------- scratch ----------------
__device__ __align__(256) float g_h  [(size_t)MR * 512];
__device__ __align__(256) float g_b2 [(size_t)MR * 512];
__device__ __align__(256) float g_big[(size_t)MR * 1024];
__device__ __align__(256) bf16 g_b1h[(size_t)MR * 512];
__device__ __align__(256) bf16 g_b1l[(size_t)MR * 512];
__device__ __align__(256) bf16 g_xh [(size_t)MR * 1024];
__device__ __align__(256) bf16 g_xl [(size_t)MR * 1024];
__device__ __align__(256) bf16 g_xbh[(size_t)MR * 64];
__device__ __align__(256) bf16 g_xbl[(size_t)MR * 64];
__device__ __align__(256) bf16 g_wbh[1024 * 512];
__device__ __align__(256) bf16 g_wbl[1024 * 512];
__device__ __align__(256) bf16 g_wch[512 * 1024];
__device__ __align__(256) bf16 g_wcl[512 * 1024];
__device__ __align__(256) bf16 g_feh[1024 * 512];
__device__ __align__(256) bf16 g_fel[1024 * 512];
__device__ __align__(256) bf16 g_fdh[512 * 512];
__device__ __align__(256) bf16 g_fdl[512 * 512];
__device__ __align__(256) bf16 g_weh[512 * 64];
__device__ __align__(256) bf16 g_wel[512 * 64];
__device__ __align__(256) float2 g_lb[512];
__device__ __align__(256) float2 g_lbN[512];
__device__ __align__(256) float2 g_carry[NBATCH * NCHK * 512];
__device__ __align__(256) float g_pool[NBATCH * NCHK * 512];

__device__ __forceinline__ float geluf(float x) {
    return 0.5f * x * (1.0f + erff(x * 0.70710678118654752f));
}
__device__ __forceinline__ uint32_t s2u(const void* p) {
    uint32_t a;
    asm("{ .reg .u64 t; cvta.to.shared.u64 t, %1; cvt.u32.u64 %0, t; }" : "=r"(a) : "l"(p));
    return a;
}
__device__ __forceinline__ void split1(float v, bf16* oh, bf16* ol) {
    bf16 h = __float2bfloat16(v);
    *oh = h;
    *ol = __float2bfloat16(v - __bfloat162float(h));
}
__device__ __forceinline__ uint32_t pack2(bf16 a, bf16 b) {
    union { bf16 h[2]; uint32_t u; } u;
    u.h[0] = a; u.h[1] = b;
    return u.u;
}
__device__ __forceinline__ void split4(float4 y, bf16* oh, bf16* ol) {
    union { bf16 b[4]; uint2 u; } H, L;
    float f[4] = {y.x, y.y, y.z, y.w};
#pragma unroll
    for (int e = 0; e < 4; e++) {
        bf16 h = __float2bfloat16(f[e]);
        H.b[e] = h;
        L.b[e] = __float2bfloat16(f[e] - __bfloat162float(h));
    }
    *(uint2*)oh = H.u;
    *(uint2*)ol = L.u;
}
__device__ __forceinline__ float2 rec2(const bf16* ph, const bf16* pl) {
    __nv_bfloat162 hh = *(const __nv_bfloat162*)ph;
    __nv_bfloat162 ll = *(const __nv_bfloat162*)pl;
    return make_float2(__bfloat162float(hh.x) + __bfloat162float(ll.x),
                       __bfloat162float(hh.y) + __bfloat162float(ll.y));
}

#define LDSM4(r0, r1, r2, r3, a) \
    asm volatile("ldmatrix.sync.aligned.m8n8.x4.shared.b16 {%0,%1,%2,%3}, [%4];" \
                 : "=r"(r0), "=r"(r1), "=r"(r2), "=r"(r3) : "r"(a))

#define MMA16816(c, a0, a1, a2, a3, b0, b1) \
    asm volatile("mma.sync.aligned.m16n8k16.row.col.f32.bf16.bf16.f32 " \
                 "{%0,%1,%2,%3}, {%4,%5,%6,%7}, {%8,%9}, {%0,%1,%2,%3};" \
                 : "+f"((c)[0]), "+f"((c)[1]), "+f"((c)[2]), "+f"((c)[3]) \
                 : "r"(a0), "r"(a1), "r"(a2), "r"(a3), "r"(b0), "r"(b1))

// ---------------- HMMA GEMM: 128x128 block, BK=32, 3-stage swizzled, 2 blocks/SM ---
// smem stage: Ah/Al/Bh/Bl, each 128 rows x 64B (XOR-swizzled 16B chunks) = 8192B.
// 3 stages x 32768 = 98304 B -> 2 blocks/SM.
// EPI: 1 +vec store fp32; 2 gelu(acc+vec[n]*u)+u (u=mh+ml); 3 C+=acc+u; 4 GEGLU->hi/lo;
//      5 local complex scan over 128-row chunk -> g_big + carry
#define MATB 8192
#define STG (4 * MATB)
#define GSMEM (3 * STG)

__device__ __forceinline__ uint32_t swadr(uint32_t row, uint32_t c16) {
    return row * 64 + ((c16 ^ ((row >> 1) & 3)) << 4);
}

template <int EPI>
__global__ void __launch_bounds__(256, 2)
gemm_tc(const bf16* __restrict__ Ah, const bf16* __restrict__ Al, int lda,
        const bf16* __restrict__ Wh, const bf16* __restrict__ Wl, int K,
        float* __restrict__ C, int ldc,
        const float* __restrict__ vec,
        const bf16* __restrict__ math, const bf16* __restrict__ matl,
        bf16* __restrict__ oh, bf16* __restrict__ ol)
{
    extern __shared__ char smembuf[];
    const uint32_t sb = s2u(smembuf);
    const int tid = threadIdx.x, lane = tid & 31, wid = tid >> 5;
    const int warpM = wid & 3, warpN = wid >> 2;
    const int bm = blockIdx.y << 7, bn = blockIdx.x << 7;
    const int NCH = K >> 5;

    float c[2][8][4];
#pragma unroll
    for (int i = 0; i < 2; i++)
#pragma unroll
        for (int j = 0; j < 8; j++)
#pragma unroll
            for (int q = 0; q < 4; q++) c[i][j][q] = 0.f;

    auto LOAD = [&](int ch) {
        if (ch < NCH) {
            uint32_t base = sb + (ch % 3) * STG;
            const bf16* gp[4] = {
                Ah + (size_t)bm * lda + ch * 32,
                Al + (size_t)bm * lda + ch * 32,
                Wh + (size_t)bn * K + ch * 32,
                Wl + (size_t)bn * K + ch * 32 };
            const int ld4[4] = {lda, lda, K, K};
#pragma unroll
            for (int mt = 0; mt < 4; mt++) {
                uint32_t mb = base + mt * MATB;
                const bf16* g = gp[mt];
                int ld = ld4[mt];
#pragma unroll
                for (int q = 0; q < 2; q++) {
                    int idx = tid + q * 256;
                    uint32_t row = idx >> 2, c16 = idx & 3;
                    uint32_t d = mb + swadr(row, c16);
                    const bf16* src = g + (size_t)row * ld + c16 * 8;
                    asm volatile("cp.async.cg.shared.global [%0], [%1], 16;"
                                 :: "r"(d), "l"(src) : "memory");
                }
            }
        }
        asm volatile("cp.async.commit_group;" ::: "memory");
    };

    LOAD(0); LOAD(1);

    for (int ch = 0; ch < NCH; ch++) {
        asm volatile("cp.async.wait_group 1;" ::: "memory");
        __syncthreads();
        LOAD(ch + 2);

        uint32_t base = sb + (ch % 3) * STG;
#pragma unroll
        for (int kk = 0; kk < 2; kk++) {
            uint32_t c16 = kk * 2 + (lane >> 4);
            uint32_t ah[2][4], al[2][4];
#pragma unroll
            for (int mf = 0; mf < 2; mf++) {
                uint32_t row = warpM * 32 + mf * 16 + (lane & 15);
                uint32_t a0 = base + swadr(row, c16);
                LDSM4(ah[mf][0], ah[mf][1], ah[mf][2], ah[mf][3], a0);
                LDSM4(al[mf][0], al[mf][1], al[mf][2], al[mf][3], a0 + MATB);
            }
#pragma unroll
            for (int g = 0; g < 4; g++) {
                uint32_t row = warpN * 64 + g * 16 + (lane & 15);
                uint32_t a0 = base + 2 * MATB + swadr(row, c16);
                uint32_t h0, h1, h2, h3, l0, l1, l2, l3;
                LDSM4(h0, h1, h2, h3, a0);
                LDSM4(l0, l1, l2, l3, a0 + MATB);
#pragma unroll
                for (int mf = 0; mf < 2; mf++) {
                    MMA16816(c[mf][2*g],   ah[mf][0], ah[mf][1], ah[mf][2], ah[mf][3], h0, h2);
                    MMA16816(c[mf][2*g+1], ah[mf][0], ah[mf][1], ah[mf][2], ah[mf][3], h1, h3);
                }
#pragma unroll
                for (int mf = 0; mf < 2; mf++) {
                    MMA16816(c[mf][2*g],   ah[mf][0], ah[mf][1], ah[mf][2], ah[mf][3], l0, l2);
                    MMA16816(c[mf][2*g+1], ah[mf][0], ah[mf][1], ah[mf][2], ah[mf][3], l1, l3);
                }
#pragma unroll
                for (int mf = 0; mf < 2; mf++) {
                    MMA16816(c[mf][2*g],   al[mf][0], al[mf][1], al[mf][2], al[mf][3], h0, h2);
                    MMA16816(c[mf][2*g+1], al[mf][0], al[mf][1], al[mf][2], al[mf][3], h1, h3);
                }
            }
        }
    }

    if (EPI == 5) {
        float* sc = (float*)smembuf;
        __syncthreads();
#pragma unroll
        for (int mf = 0; mf < 2; mf++) {
            int r0 = warpM * 32 + mf * 16 + (lane >> 2);
#pragma unroll
            for (int jb = 0; jb < 8; jb++) {
                int n = warpN * 64 + jb * 8 + 2 * (lane & 3);
#pragma unroll
                for (int half = 0; half < 2; half++) {
                    *(float2*)&sc[(r0 + half * 8) * 128 + n] =
                        make_float2(c[mf][jb][2 * half], c[mf][jb][2 * half + 1]);
                }
            }
        }
        __syncthreads();
        if (tid < 64) {
            int j = tid;
            int pglob = (bn >> 1) + j;
            float2 lb = g_lb[pglob];
            float xr = 0.f, xi = 0.f;
            float* outp = g_big + (size_t)bm * 1024 + bn + 2 * j;
#pragma unroll 4
            for (int t = 0; t < CLEN; t++) {
                float2 bu = *(float2*)&sc[t * 128 + 2 * j];
                float nr = fmaf(lb.x, xr, fmaf(-lb.y, xi, bu.x));
                float ni = fmaf(lb.x, xi, fmaf(lb.y, xr, bu.y));
                xr = nr; xi = ni;
                *(float2*)(outp + (size_t)t * 1024) = make_float2(xr, xi);
            }
            int b = bm >> 12, cch = (bm >> 7) & 31;
            g_carry[((size_t)b * NCHK + cch) * 512 + pglob] = make_float2(xr, xi);
        }
        return;
    }

    // ---------------- standard epilogues ----------------
#pragma unroll
    for (int mf = 0; mf < 2; mf++) {
        int m0 = bm + warpM * 32 + mf * 16 + (lane >> 2);
#pragma unroll
        for (int jb = 0; jb < 8; jb++) {
            int n = bn + warpN * 64 + jb * 8 + 2 * (lane & 3);
#pragma unroll
            for (int half = 0; half < 2; half++) {
                int r = m0 + half * 8;
                float v0 = c[mf][jb][2 * half], v1 = c[mf][jb][2 * half + 1];
                if (EPI == 4) {
                    int j = ((bn + warpN * 64 + jb * 8) >> 1) + (lane & 3);
                    size_t off = (size_t)r * 512 + j;
                    split1(v0 * geluf(v1), oh + off, ol + off);
                } else {
                    size_t off = (size_t)r * ldc + n;
                    if (EPI == 1) {
                        float2 bv = *(const float2*)(vec + n);
                        v0 += bv.x; v1 += bv.y;
                    } else if (EPI == 2) {
                        float2 u = rec2(math + (size_t)r * 512 + n, matl + (size_t)r * 512 + n);
                        float2 dv = *(const float2*)(vec + n);
                        v0 = geluf(v0 + dv.x * u.x) + u.x;
                        v1 = geluf(v1 + dv.y * u.y) + u.y;
                    } else if (EPI == 3) {
                        float2 u = rec2(math + (size_t)r * 512 + n, matl + (size_t)r * 512 + n);
                        float2 co = *(const float2*)(C + off);
                        v0 += co.x + u.x; v1 += co.y + u.y;
                    }
                    *(float2*)(C + off) = make_float2(v0, v1);
                }
            }
        }
    }
}

// ---------------- LayerNorm (warp per row) ----------------
__device__ __forceinline__ float wsum(float x) {
#pragma unroll
    for (int o = 16; o; o >>= 1) x += __shfl_xor_sync(0xFFFFFFFFu, x, o);
    return x;
}
__device__ __forceinline__ void ln_stage(float4 v[4], const float* __restrict__ w,
                                         const float* __restrict__ b, int l) {
    float s = 0.f;
#pragma unroll
    for (int q = 0; q < 4; q++) s += v[q].x + v[q].y + v[q].z + v[q].w;
    float mean = wsum(s) * (1.f / 512.f);
    float vv = 0.f;
#pragma unroll
    for (int q = 0; q < 4; q++) {
        v[q].x -= mean; v[q].y -= mean; v[q].z -= mean; v[q].w -= mean;
        vv += v[q].x * v[q].x + v[q].y * v[q].y + v[q].z * v[q].z + v[q].w * v[q].w;
    }
    float rs = rsqrtf(wsum(vv) * (1.f / 512.f) + 1e-5f);
#pragma unroll
    for (int q = 0; q < 4; q++) {
        int cc = (l + q * 32) * 4;
        float4 wf = *(const float4*)(w + cc);
        float4 bf = *(const float4*)(b + cc);
        v[q].x = v[q].x * rs * wf.x + bf.x;
        v[q].y = v[q].y * rs * wf.y + bf.y;
        v[q].z = v[q].z * rs * wf.z + bf.z;
        v[q].w = v[q].w * rs * wf.w + bf.w;
    }
}

template <int TWO>
__global__ void __launch_bounds__(256)
ln_kernel(const float* __restrict__ in,
          bf16* __restrict__ oh, bf16* __restrict__ ol,
          const float* __restrict__ w1, const float* __restrict__ b1,
          const float* __restrict__ w2, const float* __restrict__ b2)
{
    int row = blockIdx.x * 8 + (threadIdx.x >> 5);
    int l = threadIdx.x & 31;
    const float4* xr = (const float4*)(in + (size_t)row * 512);
    float4 v[4];
#pragma unroll
    for (int q = 0; q < 4; q++) v[q] = xr[l + q * 32];
    ln_stage(v, w1, b1, l);
    if (TWO) ln_stage(v, w2, b2, l);
#pragma unroll
    for (int q = 0; q < 4; q++) {
        size_t off = (size_t)row * 512 + (size_t)(l + q * 32) * 4;
        split4(v[q], oh + off, ol + off);
    }
}

// ---------------- consolidated per-layer prep ----------------
__device__ __forceinline__ float2 coef_of(float lr, float li, float lstep,
                                          float* lbx, float* lby)
{
    float st = expf(lstep);
    float er = expf(lr * st);
    float cc = er * cosf(li * st);
    float ss = er * sinf(li * st);
    *lbx = cc; *lby = ss;
    float den = lr * lr + li * li;
    return make_float2(((cc - 1.f) * lr + ss * li) / den, (ss * lr - (cc - 1.f) * li) / den);
}

__global__ void prep_layer(const float* __restrict__ lam_re, const float* __restrict__ lam_im,
                           const float* __restrict__ log_step,
                           const float* __restrict__ Bre, const float* __restrict__ Bim,
                           const float* __restrict__ Cre, const float* __restrict__ Cim,
                           const float* __restrict__ ffe, const float* __restrict__ ffd)
{
    int blk = blockIdx.x;
    int tid = threadIdx.x;
    if (blk < 1024) {
        int idx = blk * 256 + tid;
        int p = idx >> 9, d = idx & 511;
        float lbx, lby;
        float2 cf = coef_of(lam_re[p], lam_im[p], log_step[p], &lbx, &lby);
        float br = Bre[idx], bi = Bim[idx];
        split1(cf.x * br - cf.y * bi, &g_wbh[(size_t)(2 * p) * 512 + d], &g_wbl[(size_t)(2 * p) * 512 + d]);
        split1(cf.x * bi + cf.y * br, &g_wbh[(size_t)(2 * p + 1) * 512 + d], &g_wbl[(size_t)(2 * p + 1) * 512 + d]);
    } else if (blk < 2048) {
        int idx = (blk - 1024) * 256 + tid;
        int d = idx >> 9, p = idx & 511;
        split1(2.f * Cre[idx], &g_wch[(size_t)d * 1024 + 2 * p], &g_wcl[(size_t)d * 1024 + 2 * p]);
        split1(-2.f * Cim[idx], &g_wch[(size_t)d * 1024 + 2 * p + 1], &g_wcl[(size_t)d * 1024 + 2 * p + 1]);
    } else if (blk < 4096) {
        int idx = (blk - 2048) * 256 + tid;
        int r = idx >> 9, k = idx & 511;
        int src = (r & 1) ? (512 + (r >> 1)) : (r >> 1);
        split1(ffe[(size_t)src * 512 + k], &g_feh[(size_t)r * 512 + k], &g_fel[(size_t)r * 512 + k]);
    } else if (blk < 5120) {
        int idx = (blk - 4096) * 256 + tid;
        split1(ffd[idx], &g_fdh[idx], &g_fdl[idx]);
    } else {
        int p = (blk - 5120) * 256 + tid;
        float lbx, lby;
        coef_of(lam_re[p], lam_im[p], log_step[p], &lbx, &lby);
        g_lb[p] = make_float2(lbx, lby);
        float ar = lbx, ai = lby;
#pragma unroll
        for (int i = 0; i < 7; i++) {
            float nr = ar * ar - ai * ai, ni = 2.f * ar * ai;
            ar = nr; ai = ni;
        }
        g_lbN[p] = make_float2(ar, ai);
    }
}

__global__ void prep_enc(const float* __restrict__ w)
{
    int idx = blockIdx.x * 256 + threadIdx.x;
    if (idx >= 64 * 512) return;
    int k = idx >> 9, n = idx & 511;
    split1(w[idx], &g_weh[(size_t)n * 64 + k], &g_wel[(size_t)n * 64 + k]);
}

__global__ void cvx_kernel(const float* __restrict__ x)
{
    int idx = blockIdx.x * 256 + threadIdx.x;
    if (idx >= MR * 16) return;
    int mrow = idx >> 4, q = idx & 15;
    float4 v = *(const float4*)(x + (size_t)mrow * 64 + q * 4);
    size_t off = (size_t)mrow * 64 + (size_t)q * 4;
    split4(v, g_xbh + off, g_xbl + off);
}

// ---------------- scan combine ----------------
__global__ void scan_pass2()
{
    const int p = threadIdx.x;
    const int b = blockIdx.x;
    float2 A = g_lbN[p];
    float xr = 0.f, xi = 0.f;
#pragma unroll
    for (int c = 0; c < NCHK; c++) {
        size_t idx = ((size_t)b * NCHK + c) * 512 + p;
        float2 v = g_carry[idx];
        g_carry[idx] = make_float2(xr, xi);
        float nr = fmaf(A.x, xr, fmaf(-A.y, xi, v.x));
        float ni = fmaf(A.x, xi, fmaf(A.y, xr, v.y));
        xr = nr; xi = ni;
    }
}

__global__ void scan_pass3()
{
    const int p = threadIdx.x;
    const int c = blockIdx.x, b = blockIdx.y;
    float2 lb = g_lb[p];
    float2 cv = g_carry[((size_t)b * NCHK + c) * 512 + p];
    float pr = lb.x, pi = lb.y;
    size_t row0 = (size_t)(b * LSEQ + c * CLEN);
    const float2* loc = (const float2*)(g_big + row0 * 1024) + p;
    uint32_t* xh = (uint32_t*)(g_xh + row0 * 1024) + p;
    uint32_t* xl = (uint32_t*)(g_xl + row0 * 1024) + p;
    for (int t = 0; t < CLEN; t++) {
        float2 l = loc[(size_t)t * 512];
        float xr = fmaf(pr, cv.x, fmaf(-pi, cv.y, l.x));
        float xi = fmaf(pr, cv.y, fmaf(pi, cv.x, l.y));
        float nr = pr * lb.x - pi * lb.y;
        pi = pr * lb.y + pi * lb.x; pr = nr;
        bf16 hr = __float2bfloat16(xr);
        bf16 hi2 = __float2bfloat16(xi);
        xh[(size_t)t * 512] = pack2(hr, hi2);
        xl[(size_t)t * 512] = pack2(__float2bfloat16(xr - __bfloat162float(hr)),
                                    __float2bfloat16(xi - __bfloat162float(hi2)));
    }
}

// ---------------- pool (2-stage) + head ----------------
__global__ void pool_partial(const int* __restrict__ lengths)
{
    const int b = blockIdx.x, c = blockIdx.y;
    const int d = threadIdx.x;
    int len = lengths[b];
    int t0 = c * CLEN;
    int t1 = t0 + CLEN < len ? t0 + CLEN : len;
    float s = 0.f;
    const float* hp = g_h + ((size_t)(b * LSEQ + t0)) * 512 + d;
    for (int t = t0; t < t1; t++) { s += hp[0]; hp += 512; }
    g_pool[((size_t)b * NCHK + c) * 512 + d] = s;
}

__global__ void pool_head(const int* __restrict__ lengths,
                          const float* __restrict__ hw, const float* __restrict__ hb,
                          float* __restrict__ out)
{
    const int b = blockIdx.x;
    const int d = threadIdx.x;
    float s = 0.f;
#pragma unroll
    for (int c = 0; c < NCHK; c++) s += g_pool[((size_t)b * NCHK + c) * 512 + d];
    int len = lengths[b];
    int den = len > 1 ? len : 1;
    float v = (s / (float)den) * hw[d];
    __shared__ float red[512];
    red[d] = v; __syncthreads();
    for (int st = 256; st > 0; st >>= 1) { if (d < st) red[d] += red[d + st]; __syncthreads(); }
    if (d == 0) out[b] = red[0] + hb[0];
}

// ---------------- launch ----------------
extern "C" void kernel_launch(void* const* d_in, const int* in_sizes, int n_in,
                              void* d_out, int out_size)
{
    const float* x       = (const float*)d_in[0];
    const int*   lengths = (const int*)  d_in[1];
    const float* enc_w   = (const float*)d_in[2];
    const float* enc_b   = (const float*)d_in[3];
    const float* lam_re  = (const float*)d_in[4];
    const float* lam_im  = (const float*)d_in[5];
    const float* Bre     = (const float*)d_in[6];
    const float* Bim     = (const float*)d_in[7];
    const float* Cre     = (const float*)d_in[8];
    const float* Cim     = (const float*)d_in[9];
    const float* Dp      = (const float*)d_in[10];
    const float* log_step= (const float*)d_in[11];
    const float* an_w    = (const float*)d_in[12];
    const float* an_b    = (const float*)d_in[13];
    const float* fn_w    = (const float*)d_in[14];
    const float* fn_b    = (const float*)d_in[15];
    const float* ffe_w   = (const float*)d_in[16];
    const float* ffd_w   = (const float*)d_in[17];
    const float* norm_w  = (const float*)d_in[18];
    const float* norm_b  = (const float*)d_in[19];
    const float* head_w  = (const float*)d_in[20];
    const float* head_b  = (const float*)d_in[21];
    float* out = (float*)d_out;

    cudaFuncSetAttribute(gemm_tc<1>, cudaFuncAttributeMaxDynamicSharedMemorySize, GSMEM);
    cudaFuncSetAttribute(gemm_tc<2>, cudaFuncAttributeMaxDynamicSharedMemorySize, GSMEM);
    cudaFuncSetAttribute(gemm_tc<3>, cudaFuncAttributeMaxDynamicSharedMemorySize, GSMEM);
    cudaFuncSetAttribute(gemm_tc<4>, cudaFuncAttributeMaxDynamicSharedMemorySize, GSMEM);
    cudaFuncSetAttribute(gemm_tc<5>, cudaFuncAttributeMaxDynamicSharedMemorySize, GSMEM);

    void *p_h, *p_b2, *p_big, *p_b1h, *p_b1l, *p_xh, *p_xl, *p_xbh, *p_xbl;
    void *p_wbh, *p_wbl, *p_wch, *p_wcl, *p_feh, *p_fel, *p_fdh, *p_fdl, *p_weh, *p_wel;
    cudaGetSymbolAddress(&p_h, g_h);
    cudaGetSymbolAddress(&p_b2, g_b2);   cudaGetSymbolAddress(&p_big, g_big);
    cudaGetSymbolAddress(&p_b1h, g_b1h); cudaGetSymbolAddress(&p_b1l, g_b1l);
    cudaGetSymbolAddress(&p_xh, g_xh);   cudaGetSymbolAddress(&p_xl, g_xl);
    cudaGetSymbolAddress(&p_xbh, g_xbh); cudaGetSymbolAddress(&p_xbl, g_xbl);
    cudaGetSymbolAddress(&p_wbh, g_wbh); cudaGetSymbolAddress(&p_wbl, g_wbl);
    cudaGetSymbolAddress(&p_wch, g_wch); cudaGetSymbolAddress(&p_wcl, g_wcl);
    cudaGetSymbolAddress(&p_feh, g_feh); cudaGetSymbolAddress(&p_fel, g_fel);
    cudaGetSymbolAddress(&p_fdh, g_fdh); cudaGetSymbolAddress(&p_fdl, g_fdl);
    cudaGetSymbolAddress(&p_weh, g_weh); cudaGetSymbolAddress(&p_wel, g_wel);
    float* h   = (float*)p_h;
    float* b2  = (float*)p_b2; float* big = (float*)p_big;
    bf16* b1h = (bf16*)p_b1h; bf16* b1l = (bf16*)p_b1l;
    bf16* xh  = (bf16*)p_xh;  bf16* xl  = (bf16*)p_xl;
    bf16* xbh = (bf16*)p_xbh; bf16* xbl = (bf16*)p_xbl;
    bf16* wbh = (bf16*)p_wbh; bf16* wbl = (bf16*)p_wbl;
    bf16* wch = (bf16*)p_wch; bf16* wcl = (bf16*)p_wcl;
    bf16* feh = (bf16*)p_feh; bf16* fel = (bf16*)p_fel;
    bf16* fdh = (bf16*)p_fdh; bf16* fdl = (bf16*)p_fdl;
    bf16* weh = (bf16*)p_weh; bf16* wel = (bf16*)p_wel;

    // launch order: launch #6 (ncu -s 5 -c 1) = Bu GEMM.
    cvx_kernel<<<MR * 16 / 256, 256>>>(x);                                     // 1
    prep_enc<<<64 * 512 / 256, 256>>>(enc_w);                                  // 2
    gemm_tc<1><<<dim3(4, 256), 256, GSMEM>>>(xbh, xbl, 64, weh, wel, 64,
                                             h, 512, enc_b, nullptr, nullptr, nullptr, nullptr);  // 3

    for (int i = 0; i < NLAYER; i++) {
        prep_layer<<<5122, 256>>>(lam_re + i * 512, lam_im + i * 512, log_step + i * 512,
                                  Bre + (size_t)i * 512 * 512, Bim + (size_t)i * 512 * 512,
                                  Cre + (size_t)i * 512 * 512, Cim + (size_t)i * 512 * 512,
                                  ffe_w + (size_t)i * 1024 * 512, ffd_w + (size_t)i * 512 * 512);  // 4
        ln_kernel<1><<<MR / 8, 256>>>(h, b1h, b1l,
                                      norm_w + i * 512, norm_b + i * 512,
                                      an_w + i * 512, an_b + i * 512);                             // 5
        gemm_tc<5><<<dim3(8, 256), 256, GSMEM>>>(b1h, b1l, 512, wbh, wbl, 512,
                                                 big, 1024, nullptr, nullptr, nullptr, nullptr, nullptr);  // 6 <- ncu
        scan_pass2<<<NBATCH, 512>>>();
        scan_pass3<<<dim3(NCHK, NBATCH), 512>>>();
        gemm_tc<2><<<dim3(4, 256), 256, GSMEM>>>(xh, xl, 1024, wch, wcl, 1024,
                                                 b2, 512, Dp + i * 512, b1h, b1l, nullptr, nullptr);
        ln_kernel<0><<<MR / 8, 256>>>(b2, b1h, b1l, fn_w + i * 512, fn_b + i * 512,
                                      nullptr, nullptr);
        gemm_tc<4><<<dim3(8, 256), 256, GSMEM>>>(b1h, b1l, 512, feh, fel, 512,
                                                 nullptr, 512, nullptr, nullptr, nullptr, xh, xl);
        gemm_tc<3><<<dim3(4, 256), 256, GSMEM>>>(xh, xl, 512, fdh, fdl, 512,
                                                 h, 512, nullptr, b1h, b1l, nullptr, nullptr);
    }

    pool_partial<<<dim3(NBATCH, NCHK), 512>>>(lengths);
    pool_head<<<NBATCH, 512>>>(lengths, head_w, head_b, out);
}

// round 10
// speedup vs baseline: 2.4829x; 1.0070x over previous
#include <cuda_runtime.h>
#include <cuda_bf16.h>
#include <math.h>
#include <stdint.h>

#define MR 32768
#define LSEQ 4096
#define NBATCH 8
#define NLAYER 3
#define NCHK 32
#define CLEN 128

typedef __nv_bfloat16 bf16;

// ---------------- scratch ----------------
__device__ __align__(256) float g_h  [(size_t)MR * 512];
__device__ __align__(256) float g_b2 [(size_t)MR * 512];
__device__ __align__(256) float g_big[(size_t)MR * 1024];
__device__ __align__(256) bf16 g_b1h[(size_t)MR * 512];
__device__ __align__(256) bf16 g_b1l[(size_t)MR * 512];
__device__ __align__(256) bf16 g_xh [(size_t)MR * 1024];
__device__ __align__(256) bf16 g_xl [(size_t)MR * 1024];
__device__ __align__(256) bf16 g_xbh[(size_t)MR * 64];
__device__ __align__(256) bf16 g_xbl[(size_t)MR * 64];
__device__ __align__(256) bf16 g_wbh[1024 * 512];
__device__ __align__(256) bf16 g_wbl[1024 * 512];
__device__ __align__(256) bf16 g_wch[512 * 1024];
__device__ __align__(256) bf16 g_wcl[512 * 1024];
__device__ __align__(256) bf16 g_feh[1024 * 512];
__device__ __align__(256) bf16 g_fel[1024 * 512];
__device__ __align__(256) bf16 g_fdh[512 * 512];
__device__ __align__(256) bf16 g_fdl[512 * 512];
__device__ __align__(256) bf16 g_weh[512 * 64];
__device__ __align__(256) bf16 g_wel[512 * 64];
__device__ __align__(256) float2 g_lb[512];
__device__ __align__(256) float2 g_lbN[512];
__device__ __align__(256) float2 g_carry[NBATCH * NCHK * 512];
__device__ __align__(256) float g_pool[NBATCH * NCHK * 512];

__device__ __forceinline__ float geluf(float x) {
    return 0.5f * x * (1.0f + erff(x * 0.70710678118654752f));
}
__device__ __forceinline__ uint32_t s2u(const void* p) {
    uint32_t a;
    asm("{ .reg .u64 t; cvta.to.shared.u64 t, %1; cvt.u32.u64 %0, t; }" : "=r"(a) : "l"(p));
    return a;
}
__device__ __forceinline__ void split1(float v, bf16* oh, bf16* ol) {
    bf16 h = __float2bfloat16(v);
    *oh = h;
    *ol = __float2bfloat16(v - __bfloat162float(h));
}
__device__ __forceinline__ uint32_t pack2(bf16 a, bf16 b) {
    union { bf16 h[2]; uint32_t u; } u;
    u.h[0] = a; u.h[1] = b;
    return u.u;
}
__device__ __forceinline__ void split4(float4 y, bf16* oh, bf16* ol) {
    union { bf16 b[4]; uint2 u; } H, L;
    float f[4] = {y.x, y.y, y.z, y.w};
#pragma unroll
    for (int e = 0; e < 4; e++) {
        bf16 h = __float2bfloat16(f[e]);
        H.b[e] = h;
        L.b[e] = __float2bfloat16(f[e] - __bfloat162float(h));
    }
    *(uint2*)oh = H.u;
    *(uint2*)ol = L.u;
}
__device__ __forceinline__ float2 rec2(const bf16* ph, const bf16* pl) {
    __nv_bfloat162 hh = *(const __nv_bfloat162*)ph;
    __nv_bfloat162 ll = *(const __nv_bfloat162*)pl;
    return make_float2(__bfloat162float(hh.x) + __bfloat162float(ll.x),
                       __bfloat162float(hh.y) + __bfloat162float(ll.y));
}

#define LDSM4(r0, r1, r2, r3, a) \
    asm volatile("ldmatrix.sync.aligned.m8n8.x4.shared.b16 {%0,%1,%2,%3}, [%4];" \
                 : "=r"(r0), "=r"(r1), "=r"(r2), "=r"(r3) : "r"(a))

#define MMA16816(c, a0, a1, a2, a3, b0, b1) \
    asm volatile("mma.sync.aligned.m16n8k16.row.col.f32.bf16.bf16.f32 " \
                 "{%0,%1,%2,%3}, {%4,%5,%6,%7}, {%8,%9}, {%0,%1,%2,%3};" \
                 : "+f"((c)[0]), "+f"((c)[1]), "+f"((c)[2]), "+f"((c)[3]) \
                 : "r"(a0), "r"(a1), "r"(a2), "r"(a3), "r"(b0), "r"(b1))

// ---------------- HMMA GEMM: 128x128 block, BK=32, 3-stage swizzled, 2 blocks/SM ---
#define MATB 8192
#define STG (4 * MATB)
#define GSMEM (3 * STG)

__device__ __forceinline__ uint32_t swadr(uint32_t row, uint32_t c16) {
    return row * 64 + ((c16 ^ ((row >> 1) & 3)) << 4);
}

template <int EPI>
__global__ void __launch_bounds__(256, 2)
gemm_tc(const bf16* __restrict__ Ah, const bf16* __restrict__ Al, int lda,
        const bf16* __restrict__ Wh, const bf16* __restrict__ Wl, int K,
        float* __restrict__ C, int ldc,
        const float* __restrict__ vec,
        const bf16* __restrict__ math, const bf16* __restrict__ matl,
        bf16* __restrict__ oh, bf16* __restrict__ ol)
{
    extern __shared__ char smembuf[];
    const uint32_t sb = s2u(smembuf);
    const int tid = threadIdx.x, lane = tid & 31, wid = tid >> 5;
    const int warpM = wid & 3, warpN = wid >> 2;
    const int bm = blockIdx.y << 7, bn = blockIdx.x << 7;
    const int NCH = K >> 5;

    float c[2][8][4];
#pragma unroll
    for (int i = 0; i < 2; i++)
#pragma unroll
        for (int j = 0; j < 8; j++)
#pragma unroll
            for (int q = 0; q < 4; q++) c[i][j][q] = 0.f;

    auto LOAD = [&](int ch) {
        if (ch < NCH) {
            uint32_t base = sb + (ch % 3) * STG;
            const bf16* gp[4] = {
                Ah + (size_t)bm * lda + ch * 32,
                Al + (size_t)bm * lda + ch * 32,
                Wh + (size_t)bn * K + ch * 32,
                Wl + (size_t)bn * K + ch * 32 };
            const int ld4[4] = {lda, lda, K, K};
#pragma unroll
            for (int mt = 0; mt < 4; mt++) {
                uint32_t mb = base + mt * MATB;
                const bf16* g = gp[mt];
                int ld = ld4[mt];
#pragma unroll
                for (int q = 0; q < 2; q++) {
                    int idx = tid + q * 256;
                    uint32_t row = idx >> 2, c16 = idx & 3;
                    uint32_t d = mb + swadr(row, c16);
                    const bf16* src = g + (size_t)row * ld + c16 * 8;
                    asm volatile("cp.async.cg.shared.global [%0], [%1], 16;"
                                 :: "r"(d), "l"(src) : "memory");
                }
            }
        }
        asm volatile("cp.async.commit_group;" ::: "memory");
    };

    LOAD(0); LOAD(1);

    for (int ch = 0; ch < NCH; ch++) {
        asm volatile("cp.async.wait_group 1;" ::: "memory");
        __syncthreads();
        LOAD(ch + 2);

        uint32_t base = sb + (ch % 3) * STG;
#pragma unroll
        for (int kk = 0; kk < 2; kk++) {
            uint32_t c16 = kk * 2 + (lane >> 4);
            uint32_t ah[2][4], al[2][4];
#pragma unroll
            for (int mf = 0; mf < 2; mf++) {
                uint32_t row = warpM * 32 + mf * 16 + (lane & 15);
                uint32_t a0 = base + swadr(row, c16);
                LDSM4(ah[mf][0], ah[mf][1], ah[mf][2], ah[mf][3], a0);
                LDSM4(al[mf][0], al[mf][1], al[mf][2], al[mf][3], a0 + MATB);
            }
#pragma unroll
            for (int g = 0; g < 4; g++) {
                uint32_t row = warpN * 64 + g * 16 + (lane & 15);
                uint32_t a0 = base + 2 * MATB + swadr(row, c16);
                uint32_t h0, h1, h2, h3, l0, l1, l2, l3;
                LDSM4(h0, h1, h2, h3, a0);
                LDSM4(l0, l1, l2, l3, a0 + MATB);
#pragma unroll
                for (int mf = 0; mf < 2; mf++) {
                    MMA16816(c[mf][2*g],   ah[mf][0], ah[mf][1], ah[mf][2], ah[mf][3], h0, h2);
                    MMA16816(c[mf][2*g+1], ah[mf][0], ah[mf][1], ah[mf][2], ah[mf][3], h1, h3);
                }
#pragma unroll
                for (int mf = 0; mf < 2; mf++) {
                    MMA16816(c[mf][2*g],   ah[mf][0], ah[mf][1], ah[mf][2], ah[mf][3], l0, l2);
                    MMA16816(c[mf][2*g+1], ah[mf][0], ah[mf][1], ah[mf][2], ah[mf][3], l1, l3);
                }
#pragma unroll
                for (int mf = 0; mf < 2; mf++) {
                    MMA16816(c[mf][2*g],   al[mf][0], al[mf][1], al[mf][2], al[mf][3], h0, h2);
                    MMA16816(c[mf][2*g+1], al[mf][0], al[mf][1], al[mf][2], al[mf][3], h1, h3);
                }
            }
        }
    }

    if (EPI == 5) {
        float* sc = (float*)smembuf;
        __syncthreads();
#pragma unroll
        for (int mf = 0; mf < 2; mf++) {
            int r0 = warpM * 32 + mf * 16 + (lane >> 2);
#pragma unroll
            for (int jb = 0; jb < 8; jb++) {
                int n = warpN * 64 + jb * 8 + 2 * (lane & 3);
#pragma unroll
                for (int half = 0; half < 2; half++) {
                    *(float2*)&sc[(r0 + half * 8) * 128 + n] =
                        make_float2(c[mf][jb][2 * half], c[mf][jb][2 * half + 1]);
                }
            }
        }
        __syncthreads();
        if (tid < 64) {
            int j = tid;
            int pglob = (bn >> 1) + j;
            float2 lb = g_lb[pglob];
            float xr = 0.f, xi = 0.f;
            float* outp = g_big + (size_t)bm * 1024 + bn + 2 * j;
#pragma unroll 4
            for (int t = 0; t < CLEN; t++) {
                float2 bu = *(float2*)&sc[t * 128 + 2 * j];
                float nr = fmaf(lb.x, xr, fmaf(-lb.y, xi, bu.x));
                float ni = fmaf(lb.x, xi, fmaf(lb.y, xr, bu.y));
                xr = nr; xi = ni;
                *(float2*)(outp + (size_t)t * 1024) = make_float2(xr, xi);
            }
            int b = bm >> 12, cch = (bm >> 7) & 31;
            g_carry[((size_t)b * NCHK + cch) * 512 + pglob] = make_float2(xr, xi);
        }
        return;
    }

#pragma unroll
    for (int mf = 0; mf < 2; mf++) {
        int m0 = bm + warpM * 32 + mf * 16 + (lane >> 2);
#pragma unroll
        for (int jb = 0; jb < 8; jb++) {
            int n = bn + warpN * 64 + jb * 8 + 2 * (lane & 3);
#pragma unroll
            for (int half = 0; half < 2; half++) {
                int r = m0 + half * 8;
                float v0 = c[mf][jb][2 * half], v1 = c[mf][jb][2 * half + 1];
                if (EPI == 4) {
                    int j = ((bn + warpN * 64 + jb * 8) >> 1) + (lane & 3);
                    size_t off = (size_t)r * 512 + j;
                    split1(v0 * geluf(v1), oh + off, ol + off);
                } else {
                    size_t off = (size_t)r * ldc + n;
                    if (EPI == 1) {
                        float2 bv = *(const float2*)(vec + n);
                        v0 += bv.x; v1 += bv.y;
                    } else if (EPI == 2) {
                        float2 u = rec2(math + (size_t)r * 512 + n, matl + (size_t)r * 512 + n);
                        float2 dv = *(const float2*)(vec + n);
                        v0 = geluf(v0 + dv.x * u.x) + u.x;
                        v1 = geluf(v1 + dv.y * u.y) + u.y;
                    } else if (EPI == 3) {
                        float2 u = rec2(math + (size_t)r * 512 + n, matl + (size_t)r * 512 + n);
                        float2 co = *(const float2*)(C + off);
                        v0 += co.x + u.x; v1 += co.y + u.y;
                    }
                    *(float2*)(C + off) = make_float2(v0, v1);
                }
            }
        }
    }
}

// ---------------- LayerNorm (warp per row) ----------------
__device__ __forceinline__ float wsum(float x) {
#pragma unroll
    for (int o = 16; o; o >>= 1) x += __shfl_xor_sync(0xFFFFFFFFu, x, o);
    return x;
}
__device__ __forceinline__ void ln_stage(float4 v[4], const float* __restrict__ w,
                                         const float* __restrict__ b, int l) {
    float s = 0.f;
#pragma unroll
    for (int q = 0; q < 4; q++) s += v[q].x + v[q].y + v[q].z + v[q].w;
    float mean = wsum(s) * (1.f / 512.f);
    float vv = 0.f;
#pragma unroll
    for (int q = 0; q < 4; q++) {
        v[q].x -= mean; v[q].y -= mean; v[q].z -= mean; v[q].w -= mean;
        vv += v[q].x * v[q].x + v[q].y * v[q].y + v[q].z * v[q].z + v[q].w * v[q].w;
    }
    float rs = rsqrtf(wsum(vv) * (1.f / 512.f) + 1e-5f);
#pragma unroll
    for (int q = 0; q < 4; q++) {
        int cc = (l + q * 32) * 4;
        float4 wf = *(const float4*)(w + cc);
        float4 bf = *(const float4*)(b + cc);
        v[q].x = v[q].x * rs * wf.x + bf.x;
        v[q].y = v[q].y * rs * wf.y + bf.y;
        v[q].z = v[q].z * rs * wf.z + bf.z;
        v[q].w = v[q].w * rs * wf.w + bf.w;
    }
}

template <int TWO>
__global__ void __launch_bounds__(256)
ln_kernel(const float* __restrict__ in,
          bf16* __restrict__ oh, bf16* __restrict__ ol,
          const float* __restrict__ w1, const float* __restrict__ b1,
          const float* __restrict__ w2, const float* __restrict__ b2)
{
    int row = blockIdx.x * 8 + (threadIdx.x >> 5);
    int l = threadIdx.x & 31;
    const float4* xr = (const float4*)(in + (size_t)row * 512);
    float4 v[4];
#pragma unroll
    for (int q = 0; q < 4; q++) v[q] = xr[l + q * 32];
    ln_stage(v, w1, b1, l);
    if (TWO) ln_stage(v, w2, b2, l);
#pragma unroll
    for (int q = 0; q < 4; q++) {
        size_t off = (size_t)row * 512 + (size_t)(l + q * 32) * 4;
        split4(v[q], oh + off, ol + off);
    }
}

// ---------------- per-layer prep (device logic shared) ----------------
__device__ __forceinline__ float2 coef_of(float lr, float li, float lstep,
                                          float* lbx, float* lby)
{
    float st = expf(lstep);
    float er = expf(lr * st);
    float cc = er * cosf(li * st);
    float ss = er * sinf(li * st);
    *lbx = cc; *lby = ss;
    float den = lr * lr + li * li;
    return make_float2(((cc - 1.f) * lr + ss * li) / den, (ss * lr - (cc - 1.f) * li) / den);
}

__device__ __forceinline__ void prep_layer_body(int blk, int tid,
                           const float* __restrict__ lam_re, const float* __restrict__ lam_im,
                           const float* __restrict__ log_step,
                           const float* __restrict__ Bre, const float* __restrict__ Bim,
                           const float* __restrict__ Cre, const float* __restrict__ Cim,
                           const float* __restrict__ ffe, const float* __restrict__ ffd)
{
    if (blk < 1024) {
        int idx = blk * 256 + tid;
        int p = idx >> 9, d = idx & 511;
        float lbx, lby;
        float2 cf = coef_of(lam_re[p], lam_im[p], log_step[p], &lbx, &lby);
        float br = Bre[idx], bi = Bim[idx];
        split1(cf.x * br - cf.y * bi, &g_wbh[(size_t)(2 * p) * 512 + d], &g_wbl[(size_t)(2 * p) * 512 + d]);
        split1(cf.x * bi + cf.y * br, &g_wbh[(size_t)(2 * p + 1) * 512 + d], &g_wbl[(size_t)(2 * p + 1) * 512 + d]);
    } else if (blk < 2048) {
        int idx = (blk - 1024) * 256 + tid;
        int d = idx >> 9, p = idx & 511;
        split1(2.f * Cre[idx], &g_wch[(size_t)d * 1024 + 2 * p], &g_wcl[(size_t)d * 1024 + 2 * p]);
        split1(-2.f * Cim[idx], &g_wch[(size_t)d * 1024 + 2 * p + 1], &g_wcl[(size_t)d * 1024 + 2 * p + 1]);
    } else if (blk < 4096) {
        int idx = (blk - 2048) * 256 + tid;
        int r = idx >> 9, k = idx & 511;
        int src = (r & 1) ? (512 + (r >> 1)) : (r >> 1);
        split1(ffe[(size_t)src * 512 + k], &g_feh[(size_t)r * 512 + k], &g_fel[(size_t)r * 512 + k]);
    } else if (blk < 5120) {
        int idx = (blk - 4096) * 256 + tid;
        split1(ffd[idx], &g_fdh[idx], &g_fdl[idx]);
    } else {
        int p = (blk - 5120) * 256 + tid;
        float lbx, lby;
        coef_of(lam_re[p], lam_im[p], log_step[p], &lbx, &lby);
        g_lb[p] = make_float2(lbx, lby);
        float ar = lbx, ai = lby;
#pragma unroll
        for (int i = 0; i < 7; i++) {
            float nr = ar * ar - ai * ai, ni = 2.f * ar * ai;
            ar = nr; ai = ni;
        }
        g_lbN[p] = make_float2(ar, ai);
    }
}

__global__ void prep_layer(const float* __restrict__ lam_re, const float* __restrict__ lam_im,
                           const float* __restrict__ log_step,
                           const float* __restrict__ Bre, const float* __restrict__ Bim,
                           const float* __restrict__ Cre, const float* __restrict__ Cim,
                           const float* __restrict__ ffe, const float* __restrict__ ffd)
{
    prep_layer_body(blockIdx.x, threadIdx.x, lam_re, lam_im, log_step,
                    Bre, Bim, Cre, Cim, ffe, ffd);
}

// consolidated: cvx (2048) + enc (128) + layer-0 prep (5122) = 7298 blocks
__global__ void prep_all(const float* __restrict__ x, const float* __restrict__ enc_w,
                         const float* __restrict__ lam_re, const float* __restrict__ lam_im,
                         const float* __restrict__ log_step,
                         const float* __restrict__ Bre, const float* __restrict__ Bim,
                         const float* __restrict__ Cre, const float* __restrict__ Cim,
                         const float* __restrict__ ffe, const float* __restrict__ ffd)
{
    int blk = blockIdx.x, tid = threadIdx.x;
    if (blk < 2048) {                     // x -> bf16 hi/lo
        int idx = blk * 256 + tid;
        int mrow = idx >> 4, q = idx & 15;
        float4 v = *(const float4*)(x + (size_t)mrow * 64 + q * 4);
        size_t off = (size_t)mrow * 64 + (size_t)q * 4;
        split4(v, g_xbh + off, g_xbl + off);
    } else if (blk < 2176) {              // enc (64,512) -> (512,64) hi/lo
        int idx = (blk - 2048) * 256 + tid;
        int k = idx >> 9, n = idx & 511;
        split1(enc_w[idx], &g_weh[(size_t)n * 64 + k], &g_wel[(size_t)n * 64 + k]);
    } else {
        prep_layer_body(blk - 2176, tid, lam_re, lam_im, log_step,
                        Bre, Bim, Cre, Cim, ffe, ffd);
    }
}

// ---------------- scan combine ----------------
__global__ void scan_pass2()
{
    const int p = threadIdx.x;
    const int b = blockIdx.x;
    float2 A = g_lbN[p];
    float2 v[NCHK];
#pragma unroll
    for (int c = 0; c < NCHK; c++)
        v[c] = g_carry[((size_t)b * NCHK + c) * 512 + p];
    float xr = 0.f, xi = 0.f;
#pragma unroll
    for (int c = 0; c < NCHK; c++) {
        g_carry[((size_t)b * NCHK + c) * 512 + p] = make_float2(xr, xi);
        float nr = fmaf(A.x, xr, fmaf(-A.y, xi, v[c].x));
        float ni = fmaf(A.x, xi, fmaf(A.y, xr, v[c].y));
        xr = nr; xi = ni;
    }
}

__global__ void scan_pass3()
{
    const int p = threadIdx.x;
    const int c = blockIdx.x, b = blockIdx.y;
    float2 lb = g_lb[p];
    float2 cv = g_carry[((size_t)b * NCHK + c) * 512 + p];
    float pr = lb.x, pi = lb.y;
    size_t row0 = (size_t)(b * LSEQ + c * CLEN);
    const float2* loc = (const float2*)(g_big + row0 * 1024) + p;
    uint32_t* xh = (uint32_t*)(g_xh + row0 * 1024) + p;
    uint32_t* xl = (uint32_t*)(g_xl + row0 * 1024) + p;
    for (int t = 0; t < CLEN; t++) {
        float2 l = loc[(size_t)t * 512];
        float xr = fmaf(pr, cv.x, fmaf(-pi, cv.y, l.x));
        float xi = fmaf(pr, cv.y, fmaf(pi, cv.x, l.y));
        float nr = pr * lb.x - pi * lb.y;
        pi = pr * lb.y + pi * lb.x; pr = nr;
        bf16 hr = __float2bfloat16(xr);
        bf16 hi2 = __float2bfloat16(xi);
        xh[(size_t)t * 512] = pack2(hr, hi2);
        xl[(size_t)t * 512] = pack2(__float2bfloat16(xr - __bfloat162float(hr)),
                                    __float2bfloat16(xi - __bfloat162float(hi2)));
    }
}

// ---------------- pool (2-stage) + head ----------------
__global__ void pool_partial(const int* __restrict__ lengths)
{
    const int b = blockIdx.x, c = blockIdx.y;
    const int d = threadIdx.x;
    int len = lengths[b];
    int t0 = c * CLEN;
    int t1 = t0 + CLEN < len ? t0 + CLEN : len;
    float s = 0.f;
    const float* hp = g_h + ((size_t)(b * LSEQ + t0)) * 512 + d;
    for (int t = t0; t < t1; t++) { s += hp[0]; hp += 512; }
    g_pool[((size_t)b * NCHK + c) * 512 + d] = s;
}

__global__ void pool_head(const int* __restrict__ lengths,
                          const float* __restrict__ hw, const float* __restrict__ hb,
                          float* __restrict__ out)
{
    const int b = blockIdx.x;
    const int d = threadIdx.x;
    float s = 0.f;
#pragma unroll
    for (int c = 0; c < NCHK; c++) s += g_pool[((size_t)b * NCHK + c) * 512 + d];
    int len = lengths[b];
    int den = len > 1 ? len : 1;
    float v = (s / (float)den) * hw[d];
    __shared__ float red[512];
    red[d] = v; __syncthreads();
    for (int st = 256; st > 0; st >>= 1) { if (d < st) red[d] += red[d + st]; __syncthreads(); }
    if (d == 0) out[b] = red[0] + hb[0];
}

// ---------------- launch ----------------
extern "C" void kernel_launch(void* const* d_in, const int* in_sizes, int n_in,
                              void* d_out, int out_size)
{
    const float* x       = (const float*)d_in[0];
    const int*   lengths = (const int*)  d_in[1];
    const float* enc_w   = (const float*)d_in[2];
    const float* enc_b   = (const float*)d_in[3];
    const float* lam_re  = (const float*)d_in[4];
    const float* lam_im  = (const float*)d_in[5];
    const float* Bre     = (const float*)d_in[6];
    const float* Bim     = (const float*)d_in[7];
    const float* Cre     = (const float*)d_in[8];
    const float* Cim     = (const float*)d_in[9];
    const float* Dp      = (const float*)d_in[10];
    const float* log_step= (const float*)d_in[11];
    const float* an_w    = (const float*)d_in[12];
    const float* an_b    = (const float*)d_in[13];
    const float* fn_w    = (const float*)d_in[14];
    const float* fn_b    = (const float*)d_in[15];
    const float* ffe_w   = (const float*)d_in[16];
    const float* ffd_w   = (const float*)d_in[17];
    const float* norm_w  = (const float*)d_in[18];
    const float* norm_b  = (const float*)d_in[19];
    const float* head_w  = (const float*)d_in[20];
    const float* head_b  = (const float*)d_in[21];
    float* out = (float*)d_out;

    cudaFuncSetAttribute(gemm_tc<1>, cudaFuncAttributeMaxDynamicSharedMemorySize, GSMEM);
    cudaFuncSetAttribute(gemm_tc<2>, cudaFuncAttributeMaxDynamicSharedMemorySize, GSMEM);
    cudaFuncSetAttribute(gemm_tc<3>, cudaFuncAttributeMaxDynamicSharedMemorySize, GSMEM);
    cudaFuncSetAttribute(gemm_tc<4>, cudaFuncAttributeMaxDynamicSharedMemorySize, GSMEM);
    cudaFuncSetAttribute(gemm_tc<5>, cudaFuncAttributeMaxDynamicSharedMemorySize, GSMEM);

    void *p_h, *p_b2, *p_big, *p_b1h, *p_b1l, *p_xh, *p_xl, *p_xbh, *p_xbl;
    void *p_wbh, *p_wbl, *p_wch, *p_wcl, *p_feh, *p_fel, *p_fdh, *p_fdl, *p_weh, *p_wel;
    cudaGetSymbolAddress(&p_h, g_h);
    cudaGetSymbolAddress(&p_b2, g_b2);   cudaGetSymbolAddress(&p_big, g_big);
    cudaGetSymbolAddress(&p_b1h, g_b1h); cudaGetSymbolAddress(&p_b1l, g_b1l);
    cudaGetSymbolAddress(&p_xh, g_xh);   cudaGetSymbolAddress(&p_xl, g_xl);
    cudaGetSymbolAddress(&p_xbh, g_xbh); cudaGetSymbolAddress(&p_xbl, g_xbl);
    cudaGetSymbolAddress(&p_wbh, g_wbh); cudaGetSymbolAddress(&p_wbl, g_wbl);
    cudaGetSymbolAddress(&p_wch, g_wch); cudaGetSymbolAddress(&p_wcl, g_wcl);
    cudaGetSymbolAddress(&p_feh, g_feh); cudaGetSymbolAddress(&p_fel, g_fel);
    cudaGetSymbolAddress(&p_fdh, g_fdh); cudaGetSymbolAddress(&p_fdl, g_fdl);
    cudaGetSymbolAddress(&p_weh, g_weh); cudaGetSymbolAddress(&p_wel, g_wel);
    float* h   = (float*)p_h;
    float* b2  = (float*)p_b2; float* big = (float*)p_big;
    bf16* b1h = (bf16*)p_b1h; bf16* b1l = (bf16*)p_b1l;
    bf16* xh  = (bf16*)p_xh;  bf16* xl  = (bf16*)p_xl;
    bf16* xbh = (bf16*)p_xbh; bf16* xbl = (bf16*)p_xbl;
    bf16* wbh = (bf16*)p_wbh; bf16* wbl = (bf16*)p_wbl;
    bf16* wch = (bf16*)p_wch; bf16* wcl = (bf16*)p_wcl;
    bf16* feh = (bf16*)p_feh; bf16* fel = (bf16*)p_fel;
    bf16* fdh = (bf16*)p_fdh; bf16* fdl = (bf16*)p_fdl;
    bf16* weh = (bf16*)p_weh; bf16* wel = (bf16*)p_wel;

    // launch #1: consolidated prep (cvx + enc + layer-0 weights)
    prep_all<<<7298, 256>>>(x, enc_w, lam_re, lam_im, log_step,
                            Bre, Bim, Cre, Cim, ffe_w, ffd_w);
    // launch #2: encoder GEMM
    gemm_tc<1><<<dim3(4, 256), 256, GSMEM>>>(xbh, xbl, 64, weh, wel, 64,
                                             h, 512, enc_b, nullptr, nullptr, nullptr, nullptr);

    for (int i = 0; i < NLAYER; i++) {
        if (i > 0)
            prep_layer<<<5122, 256>>>(lam_re + i * 512, lam_im + i * 512, log_step + i * 512,
                                      Bre + (size_t)i * 512 * 512, Bim + (size_t)i * 512 * 512,
                                      Cre + (size_t)i * 512 * 512, Cim + (size_t)i * 512 * 512,
                                      ffe_w + (size_t)i * 1024 * 512, ffd_w + (size_t)i * 512 * 512);
        // launch #3 (i=0): double LN
        ln_kernel<1><<<MR / 8, 256>>>(h, b1h, b1l,
                                      norm_w + i * 512, norm_b + i * 512,
                                      an_w + i * 512, an_b + i * 512);
        // launch #4 (i=0): Bu GEMM + fused chunk-local scan  <- ncu capture target
        gemm_tc<5><<<dim3(8, 256), 256, GSMEM>>>(b1h, b1l, 512, wbh, wbl, 512,
                                                 big, 1024, nullptr, nullptr, nullptr, nullptr, nullptr);
        scan_pass2<<<NBATCH, 512>>>();
        scan_pass3<<<dim3(NCHK, NBATCH), 512>>>();
        gemm_tc<2><<<dim3(4, 256), 256, GSMEM>>>(xh, xl, 1024, wch, wcl, 1024,
                                                 b2, 512, Dp + i * 512, b1h, b1l, nullptr, nullptr);
        ln_kernel<0><<<MR / 8, 256>>>(b2, b1h, b1l, fn_w + i * 512, fn_b + i * 512,
                                      nullptr, nullptr);
        gemm_tc<4><<<dim3(8, 256), 256, GSMEM>>>(b1h, b1l, 512, feh, fel, 512,
                                                 nullptr, 512, nullptr, nullptr, nullptr, xh, xl);
        gemm_tc<3><<<dim3(4, 256), 256, GSMEM>>>(xh, xl, 512, fdh, fdl, 512,
                                                 h, 512, nullptr, b1h, b1l, nullptr, nullptr);
    }

    pool_partial<<<dim3(NBATCH, NCHK), 512>>>(lengths);
    pool_head<<<NBATCH, 512>>>(lengths, head_w, head_b, out);
}